// round 1
// baseline (speedup 1.0000x reference)
#include <cuda_runtime.h>

namespace {
constexpr int kB   = 8;
constexpr int kH   = 128;
constexpr int kW   = 128;
constexpr int kC   = 256;
constexpr int kN   = kH * kW;        // 16384 tokens per image
constexpr int kM   = kB * kN;        // 131072 rows
constexpr int kQKV = 3 * kC;         // 768
constexpr int kHD  = 32;             // head dim
constexpr float kScale = 0.17677669529663687f;  // 1/sqrt(32)
}

// Scratch (device globals -- no allocations allowed)
__device__ float g_qkv[(size_t)kM * kQKV];   // ~402 MB
__device__ float g_attn[(size_t)kM * kC];    // ~134 MB

// ---------------------------------------------------------------------------
// Generic fp32 GEMM: C[M x Nd] = A[M x Kd] @ B[Kd x Nd] (+ bias)
// 64x64 block tile, BK=32, 256 threads, 4x4 microtile.
// Assumes M % 64 == 0, Nd % 64 == 0, Kd % 32 == 0 (true for both uses).
// ---------------------------------------------------------------------------
__global__ __launch_bounds__(256, 2) void gemm64x64(
    const float* __restrict__ A, const float* __restrict__ B,
    float* __restrict__ C, int Nd, int Kd, const float* __restrict__ bias)
{
    constexpr int BK = 32;
    __shared__ float As[BK][68];   // transposed A tile: As[k][m]
    __shared__ float Bs[BK][68];   // Bs[k][n]

    const int tid = threadIdx.x;
    const int tx  = tid & 15;
    const int ty  = tid >> 4;
    const int row0 = blockIdx.y * 64;
    const int col0 = blockIdx.x * 64;

    const int a_r  = tid >> 3;   // 0..31 (+32 for second chunk)
    const int a_c4 = tid & 7;    // float4 column within BK
    const int b_r  = tid >> 4;   // 0..15 (+16 for second chunk)
    const int b_c4 = tid & 15;   // float4 column within BN

    float acc[4][4];
#pragma unroll
    for (int i = 0; i < 4; i++)
#pragma unroll
        for (int j = 0; j < 4; j++) acc[i][j] = 0.f;

    for (int k0 = 0; k0 < Kd; k0 += BK) {
#pragma unroll
        for (int i = 0; i < 2; i++) {
            int r = a_r + i * 32;
            float4 v = *(const float4*)(A + (size_t)(row0 + r) * Kd + k0 + a_c4 * 4);
            As[a_c4 * 4 + 0][r] = v.x;
            As[a_c4 * 4 + 1][r] = v.y;
            As[a_c4 * 4 + 2][r] = v.z;
            As[a_c4 * 4 + 3][r] = v.w;
        }
#pragma unroll
        for (int i = 0; i < 2; i++) {
            int r = b_r + i * 16;
            float4 v = *(const float4*)(B + (size_t)(k0 + r) * Nd + col0 + b_c4 * 4);
            *(float4*)&Bs[r][b_c4 * 4] = v;
        }
        __syncthreads();

#pragma unroll
        for (int k = 0; k < BK; k++) {
            float4 av = *(const float4*)&As[k][ty * 4];
            float4 bv = *(const float4*)&Bs[k][tx * 4];
            float a[4] = {av.x, av.y, av.z, av.w};
            float b[4] = {bv.x, bv.y, bv.z, bv.w};
#pragma unroll
            for (int i = 0; i < 4; i++)
#pragma unroll
                for (int j = 0; j < 4; j++)
                    acc[i][j] += a[i] * b[j];
        }
        __syncthreads();
    }

#pragma unroll
    for (int i = 0; i < 4; i++) {
        int r = row0 + ty * 4 + i;
        int c = col0 + tx * 4;
        float4 o = make_float4(acc[i][0], acc[i][1], acc[i][2], acc[i][3]);
        if (bias) {
            o.x += bias[c + 0];
            o.y += bias[c + 1];
            o.z += bias[c + 2];
            o.w += bias[c + 3];
        }
        *(float4*)(C + (size_t)r * Nd + c) = o;
    }
}

// ---------------------------------------------------------------------------
// Local (window) attention: heads 0..3, window 8x8 -> seq 64, hd 32.
// One block per (b, window, head), 64 threads, one query per thread.
// ---------------------------------------------------------------------------
__global__ __launch_bounds__(64) void local_attn_kernel(
    const float* __restrict__ qkv, float* __restrict__ attn)
{
    __shared__ float4 Ks[64 * 8];
    __shared__ float4 Vs[64 * 8];

    const int widx = blockIdx.x;       // 0..255
    const int head = blockIdx.y;       // 0..3
    const int b    = blockIdx.z;
    const int wy = widx >> 4, wx = widx & 15;
    const int s  = threadIdx.x;        // query index 0..63
    const int iy = s >> 3, ix = s & 7;
    const int n  = (wy * 8 + iy) * kW + (wx * 8 + ix);
    const size_t rowbase = ((size_t)b * kN + n) * kQKV + head * kHD;

    float q[32];
#pragma unroll
    for (int d4 = 0; d4 < 8; d4++) {
        float4 qv = *(const float4*)(qkv + rowbase + d4 * 4);
        q[d4 * 4 + 0] = qv.x * kScale;
        q[d4 * 4 + 1] = qv.y * kScale;
        q[d4 * 4 + 2] = qv.z * kScale;
        q[d4 * 4 + 3] = qv.w * kScale;
        Ks[s * 8 + d4] = *(const float4*)(qkv + rowbase + kC + d4 * 4);
        Vs[s * 8 + d4] = *(const float4*)(qkv + rowbase + 2 * kC + d4 * 4);
    }
    __syncthreads();

    float sc[64];
    float mx = -1e30f;
#pragma unroll
    for (int t = 0; t < 64; t++) {
        float v = 0.f;
#pragma unroll
        for (int d4 = 0; d4 < 8; d4++) {
            float4 kv = Ks[t * 8 + d4];
            v += q[d4 * 4 + 0] * kv.x + q[d4 * 4 + 1] * kv.y
               + q[d4 * 4 + 2] * kv.z + q[d4 * 4 + 3] * kv.w;
        }
        sc[t] = v;
        mx = fmaxf(mx, v);
    }
    float l = 0.f;
#pragma unroll
    for (int t = 0; t < 64; t++) {
        float p = __expf(sc[t] - mx);
        sc[t] = p;
        l += p;
    }
    const float inv = 1.f / l;

    float acc[32];
#pragma unroll
    for (int d = 0; d < 32; d++) acc[d] = 0.f;
#pragma unroll
    for (int t = 0; t < 64; t++) {
        float p = sc[t];
#pragma unroll
        for (int d4 = 0; d4 < 8; d4++) {
            float4 vv = Vs[t * 8 + d4];
            acc[d4 * 4 + 0] += p * vv.x;
            acc[d4 * 4 + 1] += p * vv.y;
            acc[d4 * 4 + 2] += p * vv.z;
            acc[d4 * 4 + 3] += p * vv.w;
        }
    }

    float* out = attn + ((size_t)b * kN + n) * kC + head * kHD;
#pragma unroll
    for (int d4 = 0; d4 < 8; d4++) {
        float4 o = make_float4(acc[d4 * 4 + 0] * inv, acc[d4 * 4 + 1] * inv,
                               acc[d4 * 4 + 2] * inv, acc[d4 * 4 + 3] * inv);
        *(float4*)(out + d4 * 4) = o;
    }
}

// ---------------------------------------------------------------------------
// Grid (global) attention: heads 4..7, seq = 16*16 = 256 windows, hd 32.
// One block per (b, intra-window position, head), 256 threads, one query per
// thread, flash-style online softmax (no score array).
// 64 KB dynamic smem for K and V.
// ---------------------------------------------------------------------------
__global__ __launch_bounds__(256) void grid_attn_kernel(
    const float* __restrict__ qkv, float* __restrict__ attn)
{
    extern __shared__ float4 smemg[];
    float4* Ks = smemg;            // [256*8]
    float4* Vs = smemg + 256 * 8;  // [256*8]

    const int gidx = blockIdx.x;        // 0..63 intra-window position
    const int head = blockIdx.y + 4;    // 4..7
    const int b    = blockIdx.z;
    const int iy = gidx >> 3, ix = gidx & 7;
    const int t  = threadIdx.x;         // window index 0..255
    const int wy = t >> 4, wx = t & 15;
    const int n  = (wy * 8 + iy) * kW + (wx * 8 + ix);
    const size_t rowbase = ((size_t)b * kN + n) * kQKV + head * kHD;

    float q[32];
#pragma unroll
    for (int d4 = 0; d4 < 8; d4++) {
        float4 qv = *(const float4*)(qkv + rowbase + d4 * 4);
        q[d4 * 4 + 0] = qv.x * kScale;
        q[d4 * 4 + 1] = qv.y * kScale;
        q[d4 * 4 + 2] = qv.z * kScale;
        q[d4 * 4 + 3] = qv.w * kScale;
        Ks[t * 8 + d4] = *(const float4*)(qkv + rowbase + kC + d4 * 4);
        Vs[t * 8 + d4] = *(const float4*)(qkv + rowbase + 2 * kC + d4 * 4);
    }
    __syncthreads();

    float m = -1e30f, l = 0.f;
    float acc[32];
#pragma unroll
    for (int d = 0; d < 32; d++) acc[d] = 0.f;

    for (int tt = 0; tt < 256; tt++) {
        float s = 0.f;
#pragma unroll
        for (int d4 = 0; d4 < 8; d4++) {
            float4 kv = Ks[tt * 8 + d4];
            s += q[d4 * 4 + 0] * kv.x + q[d4 * 4 + 1] * kv.y
               + q[d4 * 4 + 2] * kv.z + q[d4 * 4 + 3] * kv.w;
        }
        float mn   = fmaxf(m, s);
        float corr = __expf(m - mn);    // 1 when max unchanged, 0 on first iter
        float p    = __expf(s - mn);
        l = l * corr + p;
        m = mn;
#pragma unroll
        for (int d4 = 0; d4 < 8; d4++) {
            float4 vv = Vs[tt * 8 + d4];
            acc[d4 * 4 + 0] = acc[d4 * 4 + 0] * corr + p * vv.x;
            acc[d4 * 4 + 1] = acc[d4 * 4 + 1] * corr + p * vv.y;
            acc[d4 * 4 + 2] = acc[d4 * 4 + 2] * corr + p * vv.z;
            acc[d4 * 4 + 3] = acc[d4 * 4 + 3] * corr + p * vv.w;
        }
    }

    const float inv = 1.f / l;
    float* out = attn + ((size_t)b * kN + n) * kC + head * kHD;
#pragma unroll
    for (int d4 = 0; d4 < 8; d4++) {
        float4 o = make_float4(acc[d4 * 4 + 0] * inv, acc[d4 * 4 + 1] * inv,
                               acc[d4 * 4 + 2] * inv, acc[d4 * 4 + 3] * inv);
        *(float4*)(out + d4 * 4) = o;
    }
}

// ---------------------------------------------------------------------------
extern "C" void kernel_launch(void* const* d_in, const int* in_sizes, int n_in,
                              void* d_out, int out_size)
{
    const float* x     = (const float*)d_in[0];
    const float* Wqkv  = (const float*)d_in[1];
    const float* Wproj = (const float*)d_in[2];
    const float* bproj = (const float*)d_in[3];
    float* out = (float*)d_out;

    float* qkv;
    float* attn;
    cudaGetSymbolAddress((void**)&qkv, g_qkv);
    cudaGetSymbolAddress((void**)&attn, g_attn);

    // 1) qkv = x @ W_qkv
    dim3 g1(kQKV / 64, kM / 64);
    gemm64x64<<<g1, 256>>>(x, Wqkv, qkv, kQKV, kC, nullptr);

    // 2a) local window attention (heads 0..3)
    local_attn_kernel<<<dim3(256, 4, kB), 64>>>(qkv, attn);

    // 2b) global grid attention (heads 4..7)
    cudaFuncSetAttribute(grid_attn_kernel,
                         cudaFuncAttributeMaxDynamicSharedMemorySize, 65536);
    grid_attn_kernel<<<dim3(64, 4, kB), 256, 65536>>>(qkv, attn);

    // 3) out = attn @ W_proj + b_proj
    dim3 g2(kC / 64, kM / 64);
    gemm64x64<<<g2, 256>>>(attn, Wproj, out, kC, kC, bproj);
}

// round 7
// speedup vs baseline: 1.5236x; 1.5236x over previous
#include <cuda_runtime.h>
#include <cuda_fp16.h>
#include <cstdint>

namespace {
constexpr int kB   = 8;
constexpr int kH   = 128;
constexpr int kW   = 128;
constexpr int kC   = 256;
constexpr int kN   = kH * kW;        // 16384 tokens per image
constexpr int kM   = kB * kN;        // 131072 rows
constexpr int kQKV = 3 * kC;         // 768
constexpr int kHD  = 32;             // head dim
constexpr float kScale = 0.17677669529663687f;  // 1/sqrt(32)

// GEMM tiling
constexpr int BM  = 128;
constexpr int BN  = 128;
constexpr int BK  = 64;              // K chunk (K total = 256)
constexpr int LDS = 72;              // halves per smem row (64 + 8 pad) = 144B stride
constexpr int SMEM_GEMM = 4 * BM * LDS * 2;   // 73728 bytes
}

// ---------------------------------------------------------------------------
// Scratch (device globals -- no allocations allowed)
// ---------------------------------------------------------------------------
__device__ float   g_qkv[(size_t)kM * kQKV];     // fp32 qkv for attention
__device__ __half  g_x_hi[(size_t)kM * kC];
__device__ __half  g_x_lo[(size_t)kM * kC];
__device__ __half  g_a_hi[(size_t)kM * kC];      // attention out hi
__device__ __half  g_a_lo[(size_t)kM * kC];      // attention out lo
__device__ __half  g_wq_hi[(size_t)kQKV * kC];   // W_qkv^T  [768][256]
__device__ __half  g_wq_lo[(size_t)kQKV * kC];
__device__ __half  g_wp_hi[(size_t)kC * kC];     // W_proj^T [256][256]
__device__ __half  g_wp_lo[(size_t)kC * kC];

// ---------------------------------------------------------------------------
// split fp32 -> fp16 hi + fp16 lo (residual)
// ---------------------------------------------------------------------------
__device__ __forceinline__ void split1(float v, __half& h, __half& l) {
    h = __float2half_rn(v);
    l = __float2half_rn(v - __half2float(h));
}

// mma.sync m16n8k16 fp16 -> fp32 accum (base-target HMMA; no tcgen05 needed)
__device__ __forceinline__ void mma16816(float* c, const uint32_t* a, const uint32_t* b) {
    asm volatile(
        "mma.sync.aligned.m16n8k16.row.col.f32.f16.f16.f32 "
        "{%0,%1,%2,%3}, {%4,%5,%6,%7}, {%8,%9}, {%0,%1,%2,%3};"
        : "+f"(c[0]), "+f"(c[1]), "+f"(c[2]), "+f"(c[3])
        : "r"(a[0]), "r"(a[1]), "r"(a[2]), "r"(a[3]), "r"(b[0]), "r"(b[1]));
}

// ---------------------------------------------------------------------------
// Conversion kernels
// ---------------------------------------------------------------------------
__global__ void split_fp32_kernel(const float* __restrict__ src,
                                  __half* __restrict__ hi,
                                  __half* __restrict__ lo, int n)
{
    int i = (blockIdx.x * blockDim.x + threadIdx.x) * 4;
    if (i >= n) return;
    float4 v = *(const float4*)(src + i);
    __half h0, h1, h2, h3, l0, l1, l2, l3;
    split1(v.x, h0, l0); split1(v.y, h1, l1);
    split1(v.z, h2, l2); split1(v.w, h3, l3);
    *(__half2*)(hi + i)     = __halves2half2(h0, h1);
    *(__half2*)(hi + i + 2) = __halves2half2(h2, h3);
    *(__half2*)(lo + i)     = __halves2half2(l0, l1);
    *(__half2*)(lo + i + 2) = __halves2half2(l2, l3);
}

// out[n][k] = split(W[k][n]);   W is [K x N] row-major, out is [N x K]
__global__ void transpose_split_kernel(const float* __restrict__ W,
                                       __half* __restrict__ hi,
                                       __half* __restrict__ lo,
                                       int K, int N)
{
    int idx = blockIdx.x * blockDim.x + threadIdx.x;
    if (idx >= N * K) return;
    int nn = idx / K, kk = idx - nn * K;
    __half h, l;
    split1(W[(size_t)kk * N + nn], h, l);
    hi[idx] = h;
    lo[idx] = l;
}

// ---------------------------------------------------------------------------
// HMMA fp16x3 GEMM: C[M x Nd] = (Ahi+Alo)[M x 256] @ (Bhi+Blo)^T (+ bias)
// A: row-major [M][256] half (hi/lo). B^T: row-major [Nd][256] half (hi/lo).
// CTA tile 128x128, 8 warps in 4(M) x 2(N): warp tile 32x64.
// ---------------------------------------------------------------------------
__global__ __launch_bounds__(256, 1) void gemm_mma(
    const __half* __restrict__ Ahi, const __half* __restrict__ Alo,
    const __half* __restrict__ Bhi, const __half* __restrict__ Blo,
    float* __restrict__ C, int Nd, const float* __restrict__ bias)
{
    extern __shared__ __half sm[];
    __half* sAhi = sm;
    __half* sAlo = sm + 1 * BM * LDS;
    __half* sBhi = sm + 2 * BM * LDS;
    __half* sBlo = sm + 3 * BM * LDS;

    const int tid  = threadIdx.x;
    const int wid  = tid >> 5;
    const int lane = tid & 31;
    const int wm   = wid & 3;        // warp row 0..3  (32 rows each)
    const int wn   = wid >> 2;       // warp col 0..1  (64 cols each)
    const int row0 = blockIdx.y * BM;
    const int col0 = blockIdx.x * BN;

    float acc[2][8][4];
#pragma unroll
    for (int mt = 0; mt < 2; mt++)
#pragma unroll
        for (int nt = 0; nt < 8; nt++)
#pragma unroll
            for (int i = 0; i < 4; i++) acc[mt][nt][i] = 0.f;

    for (int k0 = 0; k0 < kC; k0 += BK) {
        // ---- stage chunk into smem ----
        // Each tile row needs BK=64 halves = 8 uint4; 128 rows -> 1024 uint4
        // per array; 256 threads x 4 iterations.
#pragma unroll
        for (int it = 0; it < 4; it++) {
            int u = tid + it * 256;          // 0..1023
            int r = u >> 3;                  // 0..127
            int c = (u & 7) * 8;             // half offset within chunk row (0..56)
            size_t ga = (size_t)(row0 + r) * kC + k0 + c;
            size_t gb = (size_t)(col0 + r) * kC + k0 + c;
            *(uint4*)&sAhi[r * LDS + c] = *(const uint4*)&Ahi[ga];
            *(uint4*)&sAlo[r * LDS + c] = *(const uint4*)&Alo[ga];
            *(uint4*)&sBhi[r * LDS + c] = *(const uint4*)&Bhi[gb];
            *(uint4*)&sBlo[r * LDS + c] = *(const uint4*)&Blo[gb];
        }
        __syncthreads();

#pragma unroll
        for (int ks = 0; ks < BK / 16; ks++) {
            const int kb    = ks * 16 + (lane & 3) * 2;
            const int rbase = lane >> 2;

            uint32_t ah[2][4], al[2][4];
#pragma unroll
            for (int mt = 0; mt < 2; mt++) {
                int r = wm * 32 + mt * 16 + rbase;
                ah[mt][0] = *(const uint32_t*)&sAhi[(r    ) * LDS + kb    ];
                ah[mt][1] = *(const uint32_t*)&sAhi[(r + 8) * LDS + kb    ];
                ah[mt][2] = *(const uint32_t*)&sAhi[(r    ) * LDS + kb + 8];
                ah[mt][3] = *(const uint32_t*)&sAhi[(r + 8) * LDS + kb + 8];
                al[mt][0] = *(const uint32_t*)&sAlo[(r    ) * LDS + kb    ];
                al[mt][1] = *(const uint32_t*)&sAlo[(r + 8) * LDS + kb    ];
                al[mt][2] = *(const uint32_t*)&sAlo[(r    ) * LDS + kb + 8];
                al[mt][3] = *(const uint32_t*)&sAlo[(r + 8) * LDS + kb + 8];
            }
            uint32_t bh[8][2], bl[8][2];
#pragma unroll
            for (int nt = 0; nt < 8; nt++) {
                int n = wn * 64 + nt * 8 + rbase;
                bh[nt][0] = *(const uint32_t*)&sBhi[n * LDS + kb    ];
                bh[nt][1] = *(const uint32_t*)&sBhi[n * LDS + kb + 8];
                bl[nt][0] = *(const uint32_t*)&sBlo[n * LDS + kb    ];
                bl[nt][1] = *(const uint32_t*)&sBlo[n * LDS + kb + 8];
            }
#pragma unroll
            for (int mt = 0; mt < 2; mt++)
#pragma unroll
                for (int nt = 0; nt < 8; nt++) {
                    mma16816(acc[mt][nt], ah[mt], bh[nt]);   // hi * hi
                    mma16816(acc[mt][nt], ah[mt], bl[nt]);   // hi * lo
                    mma16816(acc[mt][nt], al[mt], bh[nt]);   // lo * hi
                }
        }
        __syncthreads();
    }

    // ---- epilogue: direct fp32 stores ----
#pragma unroll
    for (int mt = 0; mt < 2; mt++) {
        int row = row0 + wm * 32 + mt * 16 + (lane >> 2);
#pragma unroll
        for (int nt = 0; nt < 8; nt++) {
            int col = col0 + wn * 64 + nt * 8 + (lane & 3) * 2;
            float2 v0 = make_float2(acc[mt][nt][0], acc[mt][nt][1]);
            float2 v1 = make_float2(acc[mt][nt][2], acc[mt][nt][3]);
            if (bias) {
                float b0 = bias[col], b1 = bias[col + 1];
                v0.x += b0; v0.y += b1;
                v1.x += b0; v1.y += b1;
            }
            *(float2*)&C[(size_t)row * Nd + col]       = v0;
            *(float2*)&C[(size_t)(row + 8) * Nd + col] = v1;
        }
    }
}

// ---------------------------------------------------------------------------
// Local (window) attention: heads 0..3, window 8x8 -> seq 64, hd 32.
// Writes fp16 hi/lo (input to proj GEMM).
// ---------------------------------------------------------------------------
__global__ __launch_bounds__(64) void local_attn_kernel(
    const float* __restrict__ qkv,
    __half* __restrict__ ahi, __half* __restrict__ alo)
{
    __shared__ float4 Ks[64 * 8];
    __shared__ float4 Vs[64 * 8];

    const int widx = blockIdx.x;       // 0..255
    const int head = blockIdx.y;       // 0..3
    const int b    = blockIdx.z;
    const int wy = widx >> 4, wx = widx & 15;
    const int s  = threadIdx.x;        // query index 0..63
    const int iy = s >> 3, ix = s & 7;
    const int n  = (wy * 8 + iy) * kW + (wx * 8 + ix);
    const size_t rowbase = ((size_t)b * kN + n) * kQKV + head * kHD;

    float q[32];
#pragma unroll
    for (int d4 = 0; d4 < 8; d4++) {
        float4 qv = *(const float4*)(qkv + rowbase + d4 * 4);
        q[d4 * 4 + 0] = qv.x * kScale;
        q[d4 * 4 + 1] = qv.y * kScale;
        q[d4 * 4 + 2] = qv.z * kScale;
        q[d4 * 4 + 3] = qv.w * kScale;
        Ks[s * 8 + d4] = *(const float4*)(qkv + rowbase + kC + d4 * 4);
        Vs[s * 8 + d4] = *(const float4*)(qkv + rowbase + 2 * kC + d4 * 4);
    }
    __syncthreads();

    float sc[64];
    float mx = -1e30f;
#pragma unroll
    for (int t = 0; t < 64; t++) {
        float v = 0.f;
#pragma unroll
        for (int d4 = 0; d4 < 8; d4++) {
            float4 kv = Ks[t * 8 + d4];
            v += q[d4 * 4 + 0] * kv.x + q[d4 * 4 + 1] * kv.y
               + q[d4 * 4 + 2] * kv.z + q[d4 * 4 + 3] * kv.w;
        }
        sc[t] = v;
        mx = fmaxf(mx, v);
    }
    float l = 0.f;
#pragma unroll
    for (int t = 0; t < 64; t++) {
        float p = __expf(sc[t] - mx);
        sc[t] = p;
        l += p;
    }
    const float inv = 1.f / l;

    float acc[32];
#pragma unroll
    for (int d = 0; d < 32; d++) acc[d] = 0.f;
#pragma unroll
    for (int t = 0; t < 64; t++) {
        float p = sc[t];
#pragma unroll
        for (int d4 = 0; d4 < 8; d4++) {
            float4 vv = Vs[t * 8 + d4];
            acc[d4 * 4 + 0] += p * vv.x;
            acc[d4 * 4 + 1] += p * vv.y;
            acc[d4 * 4 + 2] += p * vv.z;
            acc[d4 * 4 + 3] += p * vv.w;
        }
    }

    const size_t off = ((size_t)b * kN + n) * kC + head * kHD;
#pragma unroll
    for (int d4 = 0; d4 < 8; d4++) {
        __half h0, h1, h2, h3, l0, l1, l2, l3;
        split1(acc[d4 * 4 + 0] * inv, h0, l0);
        split1(acc[d4 * 4 + 1] * inv, h1, l1);
        split1(acc[d4 * 4 + 2] * inv, h2, l2);
        split1(acc[d4 * 4 + 3] * inv, h3, l3);
        *(__half2*)(ahi + off + d4 * 4)     = __halves2half2(h0, h1);
        *(__half2*)(ahi + off + d4 * 4 + 2) = __halves2half2(h2, h3);
        *(__half2*)(alo + off + d4 * 4)     = __halves2half2(l0, l1);
        *(__half2*)(alo + off + d4 * 4 + 2) = __halves2half2(l2, l3);
    }
}

// ---------------------------------------------------------------------------
// Grid (global) attention: heads 4..7, seq 256, hd 32; online softmax.
// ---------------------------------------------------------------------------
__global__ __launch_bounds__(256) void grid_attn_kernel(
    const float* __restrict__ qkv,
    __half* __restrict__ ahi, __half* __restrict__ alo)
{
    extern __shared__ float4 smemg[];
    float4* Ks = smemg;            // [256*8]
    float4* Vs = smemg + 256 * 8;  // [256*8]

    const int gidx = blockIdx.x;        // 0..63 intra-window position
    const int head = blockIdx.y + 4;    // 4..7
    const int b    = blockIdx.z;
    const int iy = gidx >> 3, ix = gidx & 7;
    const int t  = threadIdx.x;         // window index 0..255
    const int wy = t >> 4, wx = t & 15;
    const int n  = (wy * 8 + iy) * kW + (wx * 8 + ix);
    const size_t rowbase = ((size_t)b * kN + n) * kQKV + head * kHD;

    float q[32];
#pragma unroll
    for (int d4 = 0; d4 < 8; d4++) {
        float4 qv = *(const float4*)(qkv + rowbase + d4 * 4);
        q[d4 * 4 + 0] = qv.x * kScale;
        q[d4 * 4 + 1] = qv.y * kScale;
        q[d4 * 4 + 2] = qv.z * kScale;
        q[d4 * 4 + 3] = qv.w * kScale;
        Ks[t * 8 + d4] = *(const float4*)(qkv + rowbase + kC + d4 * 4);
        Vs[t * 8 + d4] = *(const float4*)(qkv + rowbase + 2 * kC + d4 * 4);
    }
    __syncthreads();

    float m = -1e30f, l = 0.f;
    float acc[32];
#pragma unroll
    for (int d = 0; d < 32; d++) acc[d] = 0.f;

    for (int tt = 0; tt < 256; tt++) {
        float s = 0.f;
#pragma unroll
        for (int d4 = 0; d4 < 8; d4++) {
            float4 kv = Ks[tt * 8 + d4];
            s += q[d4 * 4 + 0] * kv.x + q[d4 * 4 + 1] * kv.y
               + q[d4 * 4 + 2] * kv.z + q[d4 * 4 + 3] * kv.w;
        }
        float mn   = fmaxf(m, s);
        float corr = __expf(m - mn);
        float p    = __expf(s - mn);
        l = l * corr + p;
        m = mn;
#pragma unroll
        for (int d4 = 0; d4 < 8; d4++) {
            float4 vv = Vs[tt * 8 + d4];
            acc[d4 * 4 + 0] = acc[d4 * 4 + 0] * corr + p * vv.x;
            acc[d4 * 4 + 1] = acc[d4 * 4 + 1] * corr + p * vv.y;
            acc[d4 * 4 + 2] = acc[d4 * 4 + 2] * corr + p * vv.z;
            acc[d4 * 4 + 3] = acc[d4 * 4 + 3] * corr + p * vv.w;
        }
    }

    const float inv = 1.f / l;
    const size_t off = ((size_t)b * kN + n) * kC + head * kHD;
#pragma unroll
    for (int d4 = 0; d4 < 8; d4++) {
        __half h0, h1, h2, h3, l0, l1, l2, l3;
        split1(acc[d4 * 4 + 0] * inv, h0, l0);
        split1(acc[d4 * 4 + 1] * inv, h1, l1);
        split1(acc[d4 * 4 + 2] * inv, h2, l2);
        split1(acc[d4 * 4 + 3] * inv, h3, l3);
        *(__half2*)(ahi + off + d4 * 4)     = __halves2half2(h0, h1);
        *(__half2*)(ahi + off + d4 * 4 + 2) = __halves2half2(h2, h3);
        *(__half2*)(alo + off + d4 * 4)     = __halves2half2(l0, l1);
        *(__half2*)(alo + off + d4 * 4 + 2) = __halves2half2(l2, l3);
    }
}

// ---------------------------------------------------------------------------
extern "C" void kernel_launch(void* const* d_in, const int* in_sizes, int n_in,
                              void* d_out, int out_size)
{
    const float* x     = (const float*)d_in[0];
    const float* Wqkv  = (const float*)d_in[1];
    const float* Wproj = (const float*)d_in[2];
    const float* bproj = (const float*)d_in[3];
    float* out = (float*)d_out;

    float* qkv;  cudaGetSymbolAddress((void**)&qkv, g_qkv);
    __half *xhi, *xlo, *a_hi, *a_lo, *wqhi, *wqlo, *wphi, *wplo;
    cudaGetSymbolAddress((void**)&xhi,  g_x_hi);
    cudaGetSymbolAddress((void**)&xlo,  g_x_lo);
    cudaGetSymbolAddress((void**)&a_hi, g_a_hi);
    cudaGetSymbolAddress((void**)&a_lo, g_a_lo);
    cudaGetSymbolAddress((void**)&wqhi, g_wq_hi);
    cudaGetSymbolAddress((void**)&wqlo, g_wq_lo);
    cudaGetSymbolAddress((void**)&wphi, g_wp_hi);
    cudaGetSymbolAddress((void**)&wplo, g_wp_lo);

    cudaFuncSetAttribute(gemm_mma, cudaFuncAttributeMaxDynamicSharedMemorySize, SMEM_GEMM);
    cudaFuncSetAttribute(grid_attn_kernel,
                         cudaFuncAttributeMaxDynamicSharedMemorySize, 65536);

    // 0) conversions
    {
        int n = kM * kC;
        split_fp32_kernel<<<(n / 4 + 255) / 256, 256>>>(x, xhi, xlo, n);
        transpose_split_kernel<<<(kQKV * kC + 255) / 256, 256>>>(Wqkv, wqhi, wqlo, kC, kQKV);
        transpose_split_kernel<<<(kC * kC + 255) / 256, 256>>>(Wproj, wphi, wplo, kC, kC);
    }

    // 1) qkv = x @ W_qkv   (HMMA fp16x3)
    gemm_mma<<<dim3(kQKV / BN, kM / BM), 256, SMEM_GEMM>>>(
        xhi, xlo, wqhi, wqlo, qkv, kQKV, nullptr);

    // 2a) local window attention (heads 0..3)
    local_attn_kernel<<<dim3(256, 4, kB), 64>>>(qkv, a_hi, a_lo);

    // 2b) global grid attention (heads 4..7)
    grid_attn_kernel<<<dim3(64, 4, kB), 256, 65536>>>(qkv, a_hi, a_lo);

    // 3) out = attn @ W_proj + b_proj   (HMMA fp16x3)
    gemm_mma<<<dim3(kC / BN, kM / BM), 256, SMEM_GEMM>>>(
        a_hi, a_lo, wphi, wplo, out, kC, bproj);
}

// round 12
// speedup vs baseline: 1.6655x; 1.0931x over previous
#include <cuda_runtime.h>
#include <cuda_fp16.h>
#include <cstdint>

namespace {
constexpr int kB   = 8;
constexpr int kH   = 128;
constexpr int kW   = 128;
constexpr int kC   = 256;
constexpr int kN   = kH * kW;        // 16384 tokens per image
constexpr int kM   = kB * kN;        // 131072 rows
constexpr int kQKV = 3 * kC;         // 768
constexpr int kHD  = 32;             // head dim
constexpr float kScale = 0.17677669529663687f;  // 1/sqrt(32)

// GEMM tiling
constexpr int BM  = 128;
constexpr int BN  = 128;
constexpr int BK  = 64;              // K chunk (K total = 256)
constexpr int LDS = 72;              // halves per smem row (64 + 8 pad)
constexpr int SMEM_GEMM = 4 * BM * LDS * 2;   // 73728 bytes

// grid-attention smem (halves): K hi/lo [256][40], V^T hi/lo [32][264]
constexpr int GA_KSTR = 40;
constexpr int GA_VSTR = 264;
constexpr int GA_SMEM = (2 * 256 * GA_KSTR + 2 * 32 * GA_VSTR) * 2;  // 74752 B
}

// ---------------------------------------------------------------------------
// Scratch (device globals -- no allocations allowed)
// ---------------------------------------------------------------------------
__device__ float   g_qkv[(size_t)kM * kQKV];     // fp32 qkv for attention
__device__ __half  g_x_hi[(size_t)kM * kC];
__device__ __half  g_x_lo[(size_t)kM * kC];
__device__ __half  g_a_hi[(size_t)kM * kC];      // attention out hi
__device__ __half  g_a_lo[(size_t)kM * kC];      // attention out lo
__device__ __half  g_wq_hi[(size_t)kQKV * kC];   // W_qkv^T  [768][256]
__device__ __half  g_wq_lo[(size_t)kQKV * kC];
__device__ __half  g_wp_hi[(size_t)kC * kC];     // W_proj^T [256][256]
__device__ __half  g_wp_lo[(size_t)kC * kC];

// ---------------------------------------------------------------------------
__device__ __forceinline__ void split1(float v, __half& h, __half& l) {
    h = __float2half_rn(v);
    l = __float2half_rn(v - __half2float(h));
}
__device__ __forceinline__ uint32_t packh2(__half a, __half b) {
    __half2 t = __halves2half2(a, b);
    return *(uint32_t*)&t;
}
// split a float pair directly into hi-half2 / lo-half2 words
__device__ __forceinline__ void split2(float a, float b, uint32_t& hw, uint32_t& lw) {
    __half ha, la, hb, lb;
    split1(a, ha, la); split1(b, hb, lb);
    hw = packh2(ha, hb); lw = packh2(la, lb);
}

// mma.sync m16n8k16 fp16 -> fp32 accum
__device__ __forceinline__ void mma16816(float* c, const uint32_t* a, const uint32_t* b) {
    asm volatile(
        "mma.sync.aligned.m16n8k16.row.col.f32.f16.f16.f32 "
        "{%0,%1,%2,%3}, {%4,%5,%6,%7}, {%8,%9}, {%0,%1,%2,%3};"
        : "+f"(c[0]), "+f"(c[1]), "+f"(c[2]), "+f"(c[3])
        : "r"(a[0]), "r"(a[1]), "r"(a[2]), "r"(a[3]), "r"(b[0]), "r"(b[1]));
}

// ---------------------------------------------------------------------------
// Conversion kernels
// ---------------------------------------------------------------------------
__global__ void split_fp32_kernel(const float* __restrict__ src,
                                  __half* __restrict__ hi,
                                  __half* __restrict__ lo, int n)
{
    int i = (blockIdx.x * blockDim.x + threadIdx.x) * 4;
    if (i >= n) return;
    float4 v = *(const float4*)(src + i);
    uint32_t h0, l0, h1, l1;
    split2(v.x, v.y, h0, l0);
    split2(v.z, v.w, h1, l1);
    *(uint32_t*)(hi + i)     = h0;
    *(uint32_t*)(hi + i + 2) = h1;
    *(uint32_t*)(lo + i)     = l0;
    *(uint32_t*)(lo + i + 2) = l1;
}

__global__ void transpose_split_kernel(const float* __restrict__ W,
                                       __half* __restrict__ hi,
                                       __half* __restrict__ lo,
                                       int K, int N)
{
    int idx = blockIdx.x * blockDim.x + threadIdx.x;
    if (idx >= N * K) return;
    int nn = idx / K, kk = idx - nn * K;
    __half h, l;
    split1(W[(size_t)kk * N + nn], h, l);
    hi[idx] = h;
    lo[idx] = l;
}

// ---------------------------------------------------------------------------
// HMMA fp16x3 GEMM (unchanged from R7 passing version)
// ---------------------------------------------------------------------------
__global__ __launch_bounds__(256, 1) void gemm_mma(
    const __half* __restrict__ Ahi, const __half* __restrict__ Alo,
    const __half* __restrict__ Bhi, const __half* __restrict__ Blo,
    float* __restrict__ C, int Nd, const float* __restrict__ bias)
{
    extern __shared__ __half sm[];
    __half* sAhi = sm;
    __half* sAlo = sm + 1 * BM * LDS;
    __half* sBhi = sm + 2 * BM * LDS;
    __half* sBlo = sm + 3 * BM * LDS;

    const int tid  = threadIdx.x;
    const int wid  = tid >> 5;
    const int lane = tid & 31;
    const int wm   = wid & 3;
    const int wn   = wid >> 2;
    const int row0 = blockIdx.y * BM;
    const int col0 = blockIdx.x * BN;

    float acc[2][8][4];
#pragma unroll
    for (int mt = 0; mt < 2; mt++)
#pragma unroll
        for (int nt = 0; nt < 8; nt++)
#pragma unroll
            for (int i = 0; i < 4; i++) acc[mt][nt][i] = 0.f;

    for (int k0 = 0; k0 < kC; k0 += BK) {
#pragma unroll
        for (int it = 0; it < 4; it++) {
            int u = tid + it * 256;
            int r = u >> 3;
            int c = (u & 7) * 8;
            size_t ga = (size_t)(row0 + r) * kC + k0 + c;
            size_t gb = (size_t)(col0 + r) * kC + k0 + c;
            *(uint4*)&sAhi[r * LDS + c] = *(const uint4*)&Ahi[ga];
            *(uint4*)&sAlo[r * LDS + c] = *(const uint4*)&Alo[ga];
            *(uint4*)&sBhi[r * LDS + c] = *(const uint4*)&Bhi[gb];
            *(uint4*)&sBlo[r * LDS + c] = *(const uint4*)&Blo[gb];
        }
        __syncthreads();

#pragma unroll
        for (int ks = 0; ks < BK / 16; ks++) {
            const int kb    = ks * 16 + (lane & 3) * 2;
            const int rbase = lane >> 2;

            uint32_t ah[2][4], al[2][4];
#pragma unroll
            for (int mt = 0; mt < 2; mt++) {
                int r = wm * 32 + mt * 16 + rbase;
                ah[mt][0] = *(const uint32_t*)&sAhi[(r    ) * LDS + kb    ];
                ah[mt][1] = *(const uint32_t*)&sAhi[(r + 8) * LDS + kb    ];
                ah[mt][2] = *(const uint32_t*)&sAhi[(r    ) * LDS + kb + 8];
                ah[mt][3] = *(const uint32_t*)&sAhi[(r + 8) * LDS + kb + 8];
                al[mt][0] = *(const uint32_t*)&sAlo[(r    ) * LDS + kb    ];
                al[mt][1] = *(const uint32_t*)&sAlo[(r + 8) * LDS + kb    ];
                al[mt][2] = *(const uint32_t*)&sAlo[(r    ) * LDS + kb + 8];
                al[mt][3] = *(const uint32_t*)&sAlo[(r + 8) * LDS + kb + 8];
            }
            uint32_t bh[8][2], bl[8][2];
#pragma unroll
            for (int nt = 0; nt < 8; nt++) {
                int n = wn * 64 + nt * 8 + rbase;
                bh[nt][0] = *(const uint32_t*)&sBhi[n * LDS + kb    ];
                bh[nt][1] = *(const uint32_t*)&sBhi[n * LDS + kb + 8];
                bl[nt][0] = *(const uint32_t*)&sBlo[n * LDS + kb    ];
                bl[nt][1] = *(const uint32_t*)&sBlo[n * LDS + kb + 8];
            }
#pragma unroll
            for (int mt = 0; mt < 2; mt++)
#pragma unroll
                for (int nt = 0; nt < 8; nt++) {
                    mma16816(acc[mt][nt], ah[mt], bh[nt]);
                    mma16816(acc[mt][nt], ah[mt], bl[nt]);
                    mma16816(acc[mt][nt], al[mt], bh[nt]);
                }
        }
        __syncthreads();
    }

#pragma unroll
    for (int mt = 0; mt < 2; mt++) {
        int row = row0 + wm * 32 + mt * 16 + (lane >> 2);
#pragma unroll
        for (int nt = 0; nt < 8; nt++) {
            int col = col0 + wn * 64 + nt * 8 + (lane & 3) * 2;
            float2 v0 = make_float2(acc[mt][nt][0], acc[mt][nt][1]);
            float2 v1 = make_float2(acc[mt][nt][2], acc[mt][nt][3]);
            if (bias) {
                float b0 = bias[col], b1 = bias[col + 1];
                v0.x += b0; v0.y += b1;
                v1.x += b0; v1.y += b1;
            }
            *(float2*)&C[(size_t)row * Nd + col]       = v0;
            *(float2*)&C[(size_t)(row + 8) * Nd + col] = v1;
        }
    }
}

// ---------------------------------------------------------------------------
// Local (window) attention via HMMA fp16x3.
// One block per (window, head, b); 4 warps; warp w owns S rows 16w..16w+15.
// ---------------------------------------------------------------------------
__global__ __launch_bounds__(128) void local_attn_mma(
    const float* __restrict__ qkv,
    __half* __restrict__ ahi, __half* __restrict__ alo)
{
    __shared__ __half sQh[64 * 40], sQl[64 * 40];
    __shared__ __half sKh[64 * 40], sKl[64 * 40];
    __shared__ __half sVh[32 * 72], sVl[32 * 72];   // V transposed: [dim][token]

    const int widx = blockIdx.x;       // 0..255
    const int head = blockIdx.y;       // 0..3
    const int bb   = blockIdx.z;
    const int wy = widx >> 4, wx = widx & 15;
    const int tid = threadIdx.x;
    const int w = tid >> 5, lane = tid & 31;
    const int rb = lane >> 2;          // 0..7
    const int kb = (lane & 3) * 2;     // 0,2,4,6

    // ---- stage + split Q,K,V ----
    for (int idx = tid; idx < 64 * 32; idx += 128) {
        int s = idx >> 5, d = idx & 31;
        int n = (wy * 8 + (s >> 3)) * kW + wx * 8 + (s & 7);
        const float* row = qkv + ((size_t)bb * kN + n) * kQKV + head * kHD;
        __half h, l;
        split1(row[d] * kScale, h, l);  sQh[s * 40 + d] = h;  sQl[s * 40 + d] = l;
        split1(row[kC + d], h, l);      sKh[s * 40 + d] = h;  sKl[s * 40 + d] = l;
        split1(row[2 * kC + d], h, l);  sVh[d * 72 + s] = h;  sVl[d * 72 + s] = l;
    }
    __syncthreads();

    // ---- Q fragments (rows 16w..16w+15) ----
    uint32_t qh[2][4], ql[2][4];
#pragma unroll
    for (int kt = 0; kt < 2; kt++) {
        int base = (w * 16 + rb) * 40 + kt * 16 + kb;
        qh[kt][0] = *(const uint32_t*)&sQh[base];
        qh[kt][1] = *(const uint32_t*)&sQh[base + 8 * 40];
        qh[kt][2] = *(const uint32_t*)&sQh[base + 8];
        qh[kt][3] = *(const uint32_t*)&sQh[base + 8 * 40 + 8];
        ql[kt][0] = *(const uint32_t*)&sQl[base];
        ql[kt][1] = *(const uint32_t*)&sQl[base + 8 * 40];
        ql[kt][2] = *(const uint32_t*)&sQl[base + 8];
        ql[kt][3] = *(const uint32_t*)&sQl[base + 8 * 40 + 8];
    }

    // ---- S = Q K^T ----
    float sacc[8][4];
#pragma unroll
    for (int nt = 0; nt < 8; nt++)
#pragma unroll
        for (int i = 0; i < 4; i++) sacc[nt][i] = 0.f;

#pragma unroll
    for (int nt = 0; nt < 8; nt++) {
#pragma unroll
        for (int kt = 0; kt < 2; kt++) {
            int kbase = (nt * 8 + rb) * 40 + kt * 16 + kb;
            uint32_t kfh[2] = {*(const uint32_t*)&sKh[kbase],
                               *(const uint32_t*)&sKh[kbase + 8]};
            uint32_t kfl[2] = {*(const uint32_t*)&sKl[kbase],
                               *(const uint32_t*)&sKl[kbase + 8]};
            mma16816(sacc[nt], qh[kt], kfh);
            mma16816(sacc[nt], qh[kt], kfl);
            mma16816(sacc[nt], ql[kt], kfh);
        }
    }

    // ---- softmax (rows r0 = 16w+rb and r0+8) ----
    float mx0 = -1e30f, mx1 = -1e30f;
#pragma unroll
    for (int nt = 0; nt < 8; nt++) {
        mx0 = fmaxf(mx0, fmaxf(sacc[nt][0], sacc[nt][1]));
        mx1 = fmaxf(mx1, fmaxf(sacc[nt][2], sacc[nt][3]));
    }
    mx0 = fmaxf(mx0, __shfl_xor_sync(0xffffffffu, mx0, 1));
    mx0 = fmaxf(mx0, __shfl_xor_sync(0xffffffffu, mx0, 2));
    mx1 = fmaxf(mx1, __shfl_xor_sync(0xffffffffu, mx1, 1));
    mx1 = fmaxf(mx1, __shfl_xor_sync(0xffffffffu, mx1, 2));

    float sum0 = 0.f, sum1 = 0.f;
#pragma unroll
    for (int nt = 0; nt < 8; nt++) {
        sacc[nt][0] = __expf(sacc[nt][0] - mx0);
        sacc[nt][1] = __expf(sacc[nt][1] - mx0);
        sacc[nt][2] = __expf(sacc[nt][2] - mx1);
        sacc[nt][3] = __expf(sacc[nt][3] - mx1);
        sum0 += sacc[nt][0] + sacc[nt][1];
        sum1 += sacc[nt][2] + sacc[nt][3];
    }
    sum0 += __shfl_xor_sync(0xffffffffu, sum0, 1);
    sum0 += __shfl_xor_sync(0xffffffffu, sum0, 2);
    sum1 += __shfl_xor_sync(0xffffffffu, sum1, 1);
    sum1 += __shfl_xor_sync(0xffffffffu, sum1, 2);

    // ---- O = P V ----
    float oacc[4][4];
#pragma unroll
    for (int nt = 0; nt < 4; nt++)
#pragma unroll
        for (int i = 0; i < 4; i++) oacc[nt][i] = 0.f;

#pragma unroll
    for (int kt = 0; kt < 4; kt++) {
        uint32_t ph[4], pl[4];
        split2(sacc[2 * kt][0],     sacc[2 * kt][1],     ph[0], pl[0]);
        split2(sacc[2 * kt][2],     sacc[2 * kt][3],     ph[1], pl[1]);
        split2(sacc[2 * kt + 1][0], sacc[2 * kt + 1][1], ph[2], pl[2]);
        split2(sacc[2 * kt + 1][2], sacc[2 * kt + 1][3], ph[3], pl[3]);
#pragma unroll
        for (int nv = 0; nv < 4; nv++) {
            int vbase = (nv * 8 + rb) * 72 + kt * 16 + kb;
            uint32_t vfh[2] = {*(const uint32_t*)&sVh[vbase],
                               *(const uint32_t*)&sVh[vbase + 8]};
            uint32_t vfl[2] = {*(const uint32_t*)&sVl[vbase],
                               *(const uint32_t*)&sVl[vbase + 8]};
            mma16816(oacc[nv], ph, vfh);
            mma16816(oacc[nv], ph, vfl);
            mma16816(oacc[nv], pl, vfh);
        }
    }

    // ---- write (split to fp16 hi/lo) ----
    const float inv0 = 1.f / sum0, inv1 = 1.f / sum1;
    int s0 = w * 16 + rb;
    int s1 = s0 + 8;
    int n0 = (wy * 8 + (s0 >> 3)) * kW + wx * 8 + (s0 & 7);
    int n1 = (wy * 8 + (s1 >> 3)) * kW + wx * 8 + (s1 & 7);
    size_t o0 = ((size_t)bb * kN + n0) * kC + head * kHD + kb;
    size_t o1 = ((size_t)bb * kN + n1) * kC + head * kHD + kb;
#pragma unroll
    for (int nv = 0; nv < 4; nv++) {
        int c = nv * 8;
        uint32_t hw, lw;
        split2(oacc[nv][0] * inv0, oacc[nv][1] * inv0, hw, lw);
        *(uint32_t*)&ahi[o0 + c] = hw;  *(uint32_t*)&alo[o0 + c] = lw;
        split2(oacc[nv][2] * inv1, oacc[nv][3] * inv1, hw, lw);
        *(uint32_t*)&ahi[o1 + c] = hw;  *(uint32_t*)&alo[o1 + c] = lw;
    }
}

// ---------------------------------------------------------------------------
// Grid (global) attention via HMMA fp16x3, flash over 4 KV chunks of 64.
// One block per (pos, head, b); 8 warps; warp w owns rows 32w..32w+31.
// ---------------------------------------------------------------------------
__global__ __launch_bounds__(256, 1) void grid_attn_mma(
    const float* __restrict__ qkv,
    __half* __restrict__ ahi, __half* __restrict__ alo)
{
    extern __shared__ __half gsm[];
    __half* sKh = gsm;                        // [256][40]
    __half* sKl = sKh + 256 * GA_KSTR;
    __half* sVh = sKl + 256 * GA_KSTR;        // [32][264] transposed
    __half* sVl = sVh + 32 * GA_VSTR;

    const int gidx = blockIdx.x;        // 0..63 intra-window position
    const int head = blockIdx.y + 4;    // 4..7
    const int bb   = blockIdx.z;
    const int iy = gidx >> 3, ix = gidx & 7;
    const int tid = threadIdx.x;
    const int w = tid >> 5, lane = tid & 31;
    const int rb = lane >> 2;
    const int kb = (lane & 3) * 2;

    // ---- stage + split K,V (256 tokens x 32 dims) ----
    for (int idx = tid; idx < 256 * 32; idx += 256) {
        int t = idx >> 5, d = idx & 31;
        int n = ((t >> 4) * 8 + iy) * kW + (t & 15) * 8 + ix;
        const float* row = qkv + ((size_t)bb * kN + n) * kQKV + head * kHD;
        __half h, l;
        split1(row[kC + d], h, l);     sKh[t * GA_KSTR + d] = h;  sKl[t * GA_KSTR + d] = l;
        split1(row[2 * kC + d], h, l); sVh[d * GA_VSTR + t] = h;  sVl[d * GA_VSTR + t] = l;
    }

    // ---- Q fragments (rows 32w..32w+31), direct from gmem ----
    uint32_t qh[2][2][4], ql[2][2][4];
#pragma unroll
    for (int mt = 0; mt < 2; mt++) {
        int r  = w * 32 + mt * 16 + rb;
        int r8 = r + 8;
        int nA = ((r  >> 4) * 8 + iy) * kW + (r  & 15) * 8 + ix;
        int nB = ((r8 >> 4) * 8 + iy) * kW + (r8 & 15) * 8 + ix;
        const float* qA = qkv + ((size_t)bb * kN + nA) * kQKV + head * kHD;
        const float* qB = qkv + ((size_t)bb * kN + nB) * kQKV + head * kHD;
#pragma unroll
        for (int kt = 0; kt < 2; kt++) {
            float2 f;
            f = *(const float2*)&qA[kt * 16 + kb];
            split2(f.x * kScale, f.y * kScale, qh[mt][kt][0], ql[mt][kt][0]);
            f = *(const float2*)&qB[kt * 16 + kb];
            split2(f.x * kScale, f.y * kScale, qh[mt][kt][1], ql[mt][kt][1]);
            f = *(const float2*)&qA[kt * 16 + kb + 8];
            split2(f.x * kScale, f.y * kScale, qh[mt][kt][2], ql[mt][kt][2]);
            f = *(const float2*)&qB[kt * 16 + kb + 8];
            split2(f.x * kScale, f.y * kScale, qh[mt][kt][3], ql[mt][kt][3]);
        }
    }
    __syncthreads();

    float m_[4] = {-1e30f, -1e30f, -1e30f, -1e30f};
    float l_[4] = {0.f, 0.f, 0.f, 0.f};
    float oacc[2][4][4];
#pragma unroll
    for (int mt = 0; mt < 2; mt++)
#pragma unroll
        for (int nv = 0; nv < 4; nv++)
#pragma unroll
            for (int i = 0; i < 4; i++) oacc[mt][nv][i] = 0.f;

    for (int ch = 0; ch < 4; ch++) {
        // ---- S chunk ----
        float sacc[2][8][4];
#pragma unroll
        for (int mt = 0; mt < 2; mt++)
#pragma unroll
            for (int nt = 0; nt < 8; nt++)
#pragma unroll
                for (int i = 0; i < 4; i++) sacc[mt][nt][i] = 0.f;

#pragma unroll
        for (int nt = 0; nt < 8; nt++) {
#pragma unroll
            for (int kt = 0; kt < 2; kt++) {
                int kbase = (ch * 64 + nt * 8 + rb) * GA_KSTR + kt * 16 + kb;
                uint32_t kfh[2] = {*(const uint32_t*)&sKh[kbase],
                                   *(const uint32_t*)&sKh[kbase + 8]};
                uint32_t kfl[2] = {*(const uint32_t*)&sKl[kbase],
                                   *(const uint32_t*)&sKl[kbase + 8]};
#pragma unroll
                for (int mt = 0; mt < 2; mt++) {
                    mma16816(sacc[mt][nt], qh[mt][kt], kfh);
                    mma16816(sacc[mt][nt], qh[mt][kt], kfl);
                    mma16816(sacc[mt][nt], ql[mt][kt], kfh);
                }
            }
        }

        // ---- online softmax + PV per m-tile ----
#pragma unroll
        for (int mt = 0; mt < 2; mt++) {
            int i0 = 2 * mt, i1 = 2 * mt + 1;
            float cm0 = -1e30f, cm1 = -1e30f;
#pragma unroll
            for (int nt = 0; nt < 8; nt++) {
                cm0 = fmaxf(cm0, fmaxf(sacc[mt][nt][0], sacc[mt][nt][1]));
                cm1 = fmaxf(cm1, fmaxf(sacc[mt][nt][2], sacc[mt][nt][3]));
            }
            cm0 = fmaxf(cm0, __shfl_xor_sync(0xffffffffu, cm0, 1));
            cm0 = fmaxf(cm0, __shfl_xor_sync(0xffffffffu, cm0, 2));
            cm1 = fmaxf(cm1, __shfl_xor_sync(0xffffffffu, cm1, 1));
            cm1 = fmaxf(cm1, __shfl_xor_sync(0xffffffffu, cm1, 2));

            float nm0 = fmaxf(m_[i0], cm0);
            float nm1 = fmaxf(m_[i1], cm1);
            float corr0 = __expf(m_[i0] - nm0);
            float corr1 = __expf(m_[i1] - nm1);
            m_[i0] = nm0; m_[i1] = nm1;

            float s0 = 0.f, s1 = 0.f;
#pragma unroll
            for (int nt = 0; nt < 8; nt++) {
                sacc[mt][nt][0] = __expf(sacc[mt][nt][0] - nm0);
                sacc[mt][nt][1] = __expf(sacc[mt][nt][1] - nm0);
                sacc[mt][nt][2] = __expf(sacc[mt][nt][2] - nm1);
                sacc[mt][nt][3] = __expf(sacc[mt][nt][3] - nm1);
                s0 += sacc[mt][nt][0] + sacc[mt][nt][1];
                s1 += sacc[mt][nt][2] + sacc[mt][nt][3];
            }
            s0 += __shfl_xor_sync(0xffffffffu, s0, 1);
            s0 += __shfl_xor_sync(0xffffffffu, s0, 2);
            s1 += __shfl_xor_sync(0xffffffffu, s1, 1);
            s1 += __shfl_xor_sync(0xffffffffu, s1, 2);
            l_[i0] = l_[i0] * corr0 + s0;
            l_[i1] = l_[i1] * corr1 + s1;

#pragma unroll
            for (int nv = 0; nv < 4; nv++) {
                oacc[mt][nv][0] *= corr0;
                oacc[mt][nv][1] *= corr0;
                oacc[mt][nv][2] *= corr1;
                oacc[mt][nv][3] *= corr1;
            }

#pragma unroll
            for (int kt = 0; kt < 4; kt++) {
                uint32_t ph[4], pl[4];
                split2(sacc[mt][2 * kt][0],     sacc[mt][2 * kt][1],     ph[0], pl[0]);
                split2(sacc[mt][2 * kt][2],     sacc[mt][2 * kt][3],     ph[1], pl[1]);
                split2(sacc[mt][2 * kt + 1][0], sacc[mt][2 * kt + 1][1], ph[2], pl[2]);
                split2(sacc[mt][2 * kt + 1][2], sacc[mt][2 * kt + 1][3], ph[3], pl[3]);
#pragma unroll
                for (int nv = 0; nv < 4; nv++) {
                    int vbase = (nv * 8 + rb) * GA_VSTR + ch * 64 + kt * 16 + kb;
                    uint32_t vfh[2] = {*(const uint32_t*)&sVh[vbase],
                                       *(const uint32_t*)&sVh[vbase + 8]};
                    uint32_t vfl[2] = {*(const uint32_t*)&sVl[vbase],
                                       *(const uint32_t*)&sVl[vbase + 8]};
                    mma16816(oacc[mt][nv], ph, vfh);
                    mma16816(oacc[mt][nv], ph, vfl);
                    mma16816(oacc[mt][nv], pl, vfh);
                }
            }
        }
    }

    // ---- write ----
#pragma unroll
    for (int mt = 0; mt < 2; mt++) {
        float inv0 = 1.f / l_[2 * mt];
        float inv1 = 1.f / l_[2 * mt + 1];
        int r  = w * 32 + mt * 16 + rb;
        int r8 = r + 8;
        int nA = ((r  >> 4) * 8 + iy) * kW + (r  & 15) * 8 + ix;
        int nB = ((r8 >> 4) * 8 + iy) * kW + (r8 & 15) * 8 + ix;
        size_t oA = ((size_t)bb * kN + nA) * kC + head * kHD + kb;
        size_t oB = ((size_t)bb * kN + nB) * kC + head * kHD + kb;
#pragma unroll
        for (int nv = 0; nv < 4; nv++) {
            int c = nv * 8;
            uint32_t hw, lw;
            split2(oacc[mt][nv][0] * inv0, oacc[mt][nv][1] * inv0, hw, lw);
            *(uint32_t*)&ahi[oA + c] = hw;  *(uint32_t*)&alo[oA + c] = lw;
            split2(oacc[mt][nv][2] * inv1, oacc[mt][nv][3] * inv1, hw, lw);
            *(uint32_t*)&ahi[oB + c] = hw;  *(uint32_t*)&alo[oB + c] = lw;
        }
    }
}

// ---------------------------------------------------------------------------
extern "C" void kernel_launch(void* const* d_in, const int* in_sizes, int n_in,
                              void* d_out, int out_size)
{
    const float* x     = (const float*)d_in[0];
    const float* Wqkv  = (const float*)d_in[1];
    const float* Wproj = (const float*)d_in[2];
    const float* bproj = (const float*)d_in[3];
    float* out = (float*)d_out;

    float* qkv;  cudaGetSymbolAddress((void**)&qkv, g_qkv);
    __half *xhi, *xlo, *a_hi, *a_lo, *wqhi, *wqlo, *wphi, *wplo;
    cudaGetSymbolAddress((void**)&xhi,  g_x_hi);
    cudaGetSymbolAddress((void**)&xlo,  g_x_lo);
    cudaGetSymbolAddress((void**)&a_hi, g_a_hi);
    cudaGetSymbolAddress((void**)&a_lo, g_a_lo);
    cudaGetSymbolAddress((void**)&wqhi, g_wq_hi);
    cudaGetSymbolAddress((void**)&wqlo, g_wq_lo);
    cudaGetSymbolAddress((void**)&wphi, g_wp_hi);
    cudaGetSymbolAddress((void**)&wplo, g_wp_lo);

    cudaFuncSetAttribute(gemm_mma, cudaFuncAttributeMaxDynamicSharedMemorySize, SMEM_GEMM);
    cudaFuncSetAttribute(grid_attn_mma,
                         cudaFuncAttributeMaxDynamicSharedMemorySize, GA_SMEM);

    // 0) conversions
    {
        int n = kM * kC;
        split_fp32_kernel<<<(n / 4 + 255) / 256, 256>>>(x, xhi, xlo, n);
        transpose_split_kernel<<<(kQKV * kC + 255) / 256, 256>>>(Wqkv, wqhi, wqlo, kC, kQKV);
        transpose_split_kernel<<<(kC * kC + 255) / 256, 256>>>(Wproj, wphi, wplo, kC, kC);
    }

    // 1) qkv = x @ W_qkv   (HMMA fp16x3)
    gemm_mma<<<dim3(kQKV / BN, kM / BM), 256, SMEM_GEMM>>>(
        xhi, xlo, wqhi, wqlo, qkv, kQKV, nullptr);

    // 2a) local window attention (heads 0..3)  -- HMMA
    local_attn_mma<<<dim3(256, 4, kB), 128>>>(qkv, a_hi, a_lo);

    // 2b) global grid attention (heads 4..7)   -- HMMA flash
    grid_attn_mma<<<dim3(64, 4, kB), 256, GA_SMEM>>>(qkv, a_hi, a_lo);

    // 3) out = attn @ W_proj + b_proj   (HMMA fp16x3)
    gemm_mma<<<dim3(kC / BN, kM / BM), 256, SMEM_GEMM>>>(
        a_hi, a_lo, wphi, wplo, out, kC, bproj);
}

// round 15
// speedup vs baseline: 2.5767x; 1.5471x over previous
#include <cuda_runtime.h>
#include <cuda_fp16.h>
#include <cstdint>

namespace {
constexpr int kB   = 8;
constexpr int kH   = 128;
constexpr int kW   = 128;
constexpr int kC   = 256;
constexpr int kN   = kH * kW;        // 16384 tokens per image
constexpr int kM   = kB * kN;        // 131072 rows
constexpr int kQKV = 3 * kC;         // 768
constexpr int kHD  = 32;             // head dim
constexpr float kScale = 0.17677669529663687f;  // 1/sqrt(32)

// GEMM tiling
constexpr int BM   = 128;
constexpr int BN   = 128;
constexpr int BK   = 32;             // K chunk (K total = 256, 8 chunks)
constexpr int LDSB = 40;             // halves per smem row (32 + 8 pad)
constexpr int ARRH = BM * LDSB;      // halves per array (5120)
constexpr int BUFH = 4 * ARRH;       // halves per buffer (4 arrays)
constexpr int SMEM_GEMM = 2 * BUFH * 2;  // 81920 bytes (double buffered)

// grid-attention smem (halves): K hi/lo [256][40], V^T hi/lo [32][264]
constexpr int GA_KSTR = 40;
constexpr int GA_VSTR = 264;
constexpr int GA_SMEM = (2 * 256 * GA_KSTR + 2 * 32 * GA_VSTR) * 2;  // 74752 B
}

// ---------------------------------------------------------------------------
// Scratch (device globals -- no allocations allowed)
// ---------------------------------------------------------------------------
__device__ float   g_qkv[(size_t)kM * kQKV];     // fp32 qkv for attention
__device__ __half  g_x_hi[(size_t)kM * kC];
__device__ __half  g_x_lo[(size_t)kM * kC];
__device__ __half  g_a_hi[(size_t)kM * kC];      // attention out hi
__device__ __half  g_a_lo[(size_t)kM * kC];      // attention out lo
__device__ __half  g_wq_hi[(size_t)kQKV * kC];   // W_qkv^T  [768][256]
__device__ __half  g_wq_lo[(size_t)kQKV * kC];
__device__ __half  g_wp_hi[(size_t)kC * kC];     // W_proj^T [256][256]
__device__ __half  g_wp_lo[(size_t)kC * kC];

// ---------------------------------------------------------------------------
__device__ __forceinline__ void split1(float v, __half& h, __half& l) {
    h = __float2half_rn(v);
    l = __float2half_rn(v - __half2float(h));
}
__device__ __forceinline__ uint32_t packh2(__half a, __half b) {
    __half2 t = __halves2half2(a, b);
    return *(uint32_t*)&t;
}
__device__ __forceinline__ void split2(float a, float b, uint32_t& hw, uint32_t& lw) {
    __half ha, la, hb, lb;
    split1(a, ha, la); split1(b, hb, lb);
    hw = packh2(ha, hb); lw = packh2(la, lb);
}

__device__ __forceinline__ void mma16816(float* c, const uint32_t* a, const uint32_t* b) {
    asm volatile(
        "mma.sync.aligned.m16n8k16.row.col.f32.f16.f16.f32 "
        "{%0,%1,%2,%3}, {%4,%5,%6,%7}, {%8,%9}, {%0,%1,%2,%3};"
        : "+f"(c[0]), "+f"(c[1]), "+f"(c[2]), "+f"(c[3])
        : "r"(a[0]), "r"(a[1]), "r"(a[2]), "r"(a[3]), "r"(b[0]), "r"(b[1]));
}

__device__ __forceinline__ uint32_t smem_u32(const void* p) {
    uint32_t a;
    asm("{ .reg .u64 t; cvta.to.shared.u64 t, %1; cvt.u32.u64 %0, t; }"
        : "=r"(a) : "l"(p));
    return a;
}
__device__ __forceinline__ void cp16(uint32_t s, const void* g) {
    asm volatile("cp.async.cg.shared.global [%0], [%1], 16;" :: "r"(s), "l"(g));
}
#define CP_COMMIT() asm volatile("cp.async.commit_group;" ::: "memory")
#define CP_WAIT(n)  asm volatile("cp.async.wait_group %0;" :: "n"(n) : "memory")

// ---------------------------------------------------------------------------
// Conversion kernels
// ---------------------------------------------------------------------------
__global__ void split_fp32_kernel(const float* __restrict__ src,
                                  __half* __restrict__ hi,
                                  __half* __restrict__ lo, int n)
{
    int i = (blockIdx.x * blockDim.x + threadIdx.x) * 4;
    if (i >= n) return;
    float4 v = *(const float4*)(src + i);
    uint32_t h0, l0, h1, l1;
    split2(v.x, v.y, h0, l0);
    split2(v.z, v.w, h1, l1);
    *(uint32_t*)(hi + i)     = h0;
    *(uint32_t*)(hi + i + 2) = h1;
    *(uint32_t*)(lo + i)     = l0;
    *(uint32_t*)(lo + i + 2) = l1;
}

__global__ void transpose_split_kernel(const float* __restrict__ W,
                                       __half* __restrict__ hi,
                                       __half* __restrict__ lo,
                                       int K, int N)
{
    int idx = blockIdx.x * blockDim.x + threadIdx.x;
    if (idx >= N * K) return;
    int nn = idx / K, kk = idx - nn * K;
    __half h, l;
    split1(W[(size_t)kk * N + nn], h, l);
    hi[idx] = h;
    lo[idx] = l;
}

// ---------------------------------------------------------------------------
// HMMA fp16x3 GEMM, double-buffered cp.async, 2 CTAs/SM.
// C[M x Nd] = (Ahi+Alo)[M x 256] @ (Bhi+Blo)^T (+ bias)
// CTA tile 128x128, 8 warps in 4(M) x 2(N): warp tile 32x64.
// ---------------------------------------------------------------------------
__global__ __launch_bounds__(256, 2) void gemm_mma(
    const __half* __restrict__ Ahi, const __half* __restrict__ Alo,
    const __half* __restrict__ Bhi, const __half* __restrict__ Blo,
    float* __restrict__ C, int Nd, const float* __restrict__ bias)
{
    extern __shared__ __half sm[];

    const int tid  = threadIdx.x;
    const int wid  = tid >> 5;
    const int lane = tid & 31;
    const int wm   = wid & 3;
    const int wn   = wid >> 2;
    const int row0 = blockIdx.y * BM;
    const int col0 = blockIdx.x * BN;

    // staging coordinates: 512 uint4 per array, 256 threads x 2
    const int sr0 = tid >> 2;              // row for it=0 (0..63)
    const int sc  = (tid & 3) * 8;         // half offset (0,8,16,24)

    float acc[2][8][4];
#pragma unroll
    for (int mt = 0; mt < 2; mt++)
#pragma unroll
        for (int nt = 0; nt < 8; nt++)
#pragma unroll
            for (int i = 0; i < 4; i++) acc[mt][nt][i] = 0.f;

    // issue loads for chunk `ch` into buffer `buf`
    auto issue = [&](int ch, int buf) {
        __half* base = sm + buf * BUFH;
        uint32_t sA_hi = smem_u32(base);
        uint32_t sA_lo = smem_u32(base + ARRH);
        uint32_t sB_hi = smem_u32(base + 2 * ARRH);
        uint32_t sB_lo = smem_u32(base + 3 * ARRH);
#pragma unroll
        for (int it = 0; it < 2; it++) {
            int r = sr0 + it * 64;
            uint32_t so = (uint32_t)(r * LDSB + sc) * 2;
            size_t ga = (size_t)(row0 + r) * kC + ch * BK + sc;
            size_t gb = (size_t)(col0 + r) * kC + ch * BK + sc;
            cp16(sA_hi + so, Ahi + ga);
            cp16(sA_lo + so, Alo + ga);
            cp16(sB_hi + so, Bhi + gb);
            cp16(sB_lo + so, Blo + gb);
        }
        CP_COMMIT();
    };

    issue(0, 0);

    for (int ch = 0; ch < 8; ch++) {
        const int buf = ch & 1;
        if (ch + 1 < 8) {
            issue(ch + 1, buf ^ 1);
            CP_WAIT(1);
        } else {
            CP_WAIT(0);
        }
        __syncthreads();

        const __half* sAhi = sm + buf * BUFH;
        const __half* sAlo = sAhi + ARRH;
        const __half* sBhi = sAhi + 2 * ARRH;
        const __half* sBlo = sAhi + 3 * ARRH;

#pragma unroll
        for (int ks = 0; ks < BK / 16; ks++) {
            const int kb    = ks * 16 + (lane & 3) * 2;
            const int rbase = lane >> 2;

            uint32_t ah[2][4], al[2][4];
#pragma unroll
            for (int mt = 0; mt < 2; mt++) {
                int r = wm * 32 + mt * 16 + rbase;
                ah[mt][0] = *(const uint32_t*)&sAhi[(r    ) * LDSB + kb    ];
                ah[mt][1] = *(const uint32_t*)&sAhi[(r + 8) * LDSB + kb    ];
                ah[mt][2] = *(const uint32_t*)&sAhi[(r    ) * LDSB + kb + 8];
                ah[mt][3] = *(const uint32_t*)&sAhi[(r + 8) * LDSB + kb + 8];
                al[mt][0] = *(const uint32_t*)&sAlo[(r    ) * LDSB + kb    ];
                al[mt][1] = *(const uint32_t*)&sAlo[(r + 8) * LDSB + kb    ];
                al[mt][2] = *(const uint32_t*)&sAlo[(r    ) * LDSB + kb + 8];
                al[mt][3] = *(const uint32_t*)&sAlo[(r + 8) * LDSB + kb + 8];
            }
#pragma unroll
            for (int nt = 0; nt < 8; nt++) {
                int n = wn * 64 + nt * 8 + rbase;
                uint32_t bh[2] = {*(const uint32_t*)&sBhi[n * LDSB + kb],
                                  *(const uint32_t*)&sBhi[n * LDSB + kb + 8]};
                uint32_t bl[2] = {*(const uint32_t*)&sBlo[n * LDSB + kb],
                                  *(const uint32_t*)&sBlo[n * LDSB + kb + 8]};
#pragma unroll
                for (int mt = 0; mt < 2; mt++) {
                    mma16816(acc[mt][nt], ah[mt], bh);
                    mma16816(acc[mt][nt], ah[mt], bl);
                    mma16816(acc[mt][nt], al[mt], bh);
                }
            }
        }
        __syncthreads();
    }

#pragma unroll
    for (int mt = 0; mt < 2; mt++) {
        int row = row0 + wm * 32 + mt * 16 + (lane >> 2);
#pragma unroll
        for (int nt = 0; nt < 8; nt++) {
            int col = col0 + wn * 64 + nt * 8 + (lane & 3) * 2;
            float2 v0 = make_float2(acc[mt][nt][0], acc[mt][nt][1]);
            float2 v1 = make_float2(acc[mt][nt][2], acc[mt][nt][3]);
            if (bias) {
                float b0 = bias[col], b1 = bias[col + 1];
                v0.x += b0; v0.y += b1;
                v1.x += b0; v1.y += b1;
            }
            *(float2*)&C[(size_t)row * Nd + col]       = v0;
            *(float2*)&C[(size_t)(row + 8) * Nd + col] = v1;
        }
    }
}

// ---------------------------------------------------------------------------
// Local (window) attention via HMMA fp16x3 (unchanged, passing).
// ---------------------------------------------------------------------------
__global__ __launch_bounds__(128) void local_attn_mma(
    const float* __restrict__ qkv,
    __half* __restrict__ ahi, __half* __restrict__ alo)
{
    __shared__ __half sQh[64 * 40], sQl[64 * 40];
    __shared__ __half sKh[64 * 40], sKl[64 * 40];
    __shared__ __half sVh[32 * 72], sVl[32 * 72];

    const int widx = blockIdx.x;
    const int head = blockIdx.y;
    const int bb   = blockIdx.z;
    const int wy = widx >> 4, wx = widx & 15;
    const int tid = threadIdx.x;
    const int w = tid >> 5, lane = tid & 31;
    const int rb = lane >> 2;
    const int kb = (lane & 3) * 2;

    for (int idx = tid; idx < 64 * 32; idx += 128) {
        int s = idx >> 5, d = idx & 31;
        int n = (wy * 8 + (s >> 3)) * kW + wx * 8 + (s & 7);
        const float* row = qkv + ((size_t)bb * kN + n) * kQKV + head * kHD;
        __half h, l;
        split1(row[d] * kScale, h, l);  sQh[s * 40 + d] = h;  sQl[s * 40 + d] = l;
        split1(row[kC + d], h, l);      sKh[s * 40 + d] = h;  sKl[s * 40 + d] = l;
        split1(row[2 * kC + d], h, l);  sVh[d * 72 + s] = h;  sVl[d * 72 + s] = l;
    }
    __syncthreads();

    uint32_t qh[2][4], ql[2][4];
#pragma unroll
    for (int kt = 0; kt < 2; kt++) {
        int base = (w * 16 + rb) * 40 + kt * 16 + kb;
        qh[kt][0] = *(const uint32_t*)&sQh[base];
        qh[kt][1] = *(const uint32_t*)&sQh[base + 8 * 40];
        qh[kt][2] = *(const uint32_t*)&sQh[base + 8];
        qh[kt][3] = *(const uint32_t*)&sQh[base + 8 * 40 + 8];
        ql[kt][0] = *(const uint32_t*)&sQl[base];
        ql[kt][1] = *(const uint32_t*)&sQl[base + 8 * 40];
        ql[kt][2] = *(const uint32_t*)&sQl[base + 8];
        ql[kt][3] = *(const uint32_t*)&sQl[base + 8 * 40 + 8];
    }

    float sacc[8][4];
#pragma unroll
    for (int nt = 0; nt < 8; nt++)
#pragma unroll
        for (int i = 0; i < 4; i++) sacc[nt][i] = 0.f;

#pragma unroll
    for (int nt = 0; nt < 8; nt++) {
#pragma unroll
        for (int kt = 0; kt < 2; kt++) {
            int kbase = (nt * 8 + rb) * 40 + kt * 16 + kb;
            uint32_t kfh[2] = {*(const uint32_t*)&sKh[kbase],
                               *(const uint32_t*)&sKh[kbase + 8]};
            uint32_t kfl[2] = {*(const uint32_t*)&sKl[kbase],
                               *(const uint32_t*)&sKl[kbase + 8]};
            mma16816(sacc[nt], qh[kt], kfh);
            mma16816(sacc[nt], qh[kt], kfl);
            mma16816(sacc[nt], ql[kt], kfh);
        }
    }

    float mx0 = -1e30f, mx1 = -1e30f;
#pragma unroll
    for (int nt = 0; nt < 8; nt++) {
        mx0 = fmaxf(mx0, fmaxf(sacc[nt][0], sacc[nt][1]));
        mx1 = fmaxf(mx1, fmaxf(sacc[nt][2], sacc[nt][3]));
    }
    mx0 = fmaxf(mx0, __shfl_xor_sync(0xffffffffu, mx0, 1));
    mx0 = fmaxf(mx0, __shfl_xor_sync(0xffffffffu, mx0, 2));
    mx1 = fmaxf(mx1, __shfl_xor_sync(0xffffffffu, mx1, 1));
    mx1 = fmaxf(mx1, __shfl_xor_sync(0xffffffffu, mx1, 2));

    float sum0 = 0.f, sum1 = 0.f;
#pragma unroll
    for (int nt = 0; nt < 8; nt++) {
        sacc[nt][0] = __expf(sacc[nt][0] - mx0);
        sacc[nt][1] = __expf(sacc[nt][1] - mx0);
        sacc[nt][2] = __expf(sacc[nt][2] - mx1);
        sacc[nt][3] = __expf(sacc[nt][3] - mx1);
        sum0 += sacc[nt][0] + sacc[nt][1];
        sum1 += sacc[nt][2] + sacc[nt][3];
    }
    sum0 += __shfl_xor_sync(0xffffffffu, sum0, 1);
    sum0 += __shfl_xor_sync(0xffffffffu, sum0, 2);
    sum1 += __shfl_xor_sync(0xffffffffu, sum1, 1);
    sum1 += __shfl_xor_sync(0xffffffffu, sum1, 2);

    float oacc[4][4];
#pragma unroll
    for (int nt = 0; nt < 4; nt++)
#pragma unroll
        for (int i = 0; i < 4; i++) oacc[nt][i] = 0.f;

#pragma unroll
    for (int kt = 0; kt < 4; kt++) {
        uint32_t ph[4], pl[4];
        split2(sacc[2 * kt][0],     sacc[2 * kt][1],     ph[0], pl[0]);
        split2(sacc[2 * kt][2],     sacc[2 * kt][3],     ph[1], pl[1]);
        split2(sacc[2 * kt + 1][0], sacc[2 * kt + 1][1], ph[2], pl[2]);
        split2(sacc[2 * kt + 1][2], sacc[2 * kt + 1][3], ph[3], pl[3]);
#pragma unroll
        for (int nv = 0; nv < 4; nv++) {
            int vbase = (nv * 8 + rb) * 72 + kt * 16 + kb;
            uint32_t vfh[2] = {*(const uint32_t*)&sVh[vbase],
                               *(const uint32_t*)&sVh[vbase + 8]};
            uint32_t vfl[2] = {*(const uint32_t*)&sVl[vbase],
                               *(const uint32_t*)&sVl[vbase + 8]};
            mma16816(oacc[nv], ph, vfh);
            mma16816(oacc[nv], ph, vfl);
            mma16816(oacc[nv], pl, vfh);
        }
    }

    const float inv0 = 1.f / sum0, inv1 = 1.f / sum1;
    int s0 = w * 16 + rb;
    int s1 = s0 + 8;
    int n0 = (wy * 8 + (s0 >> 3)) * kW + wx * 8 + (s0 & 7);
    int n1 = (wy * 8 + (s1 >> 3)) * kW + wx * 8 + (s1 & 7);
    size_t o0 = ((size_t)bb * kN + n0) * kC + head * kHD + kb;
    size_t o1 = ((size_t)bb * kN + n1) * kC + head * kHD + kb;
#pragma unroll
    for (int nv = 0; nv < 4; nv++) {
        int c = nv * 8;
        uint32_t hw, lw;
        split2(oacc[nv][0] * inv0, oacc[nv][1] * inv0, hw, lw);
        *(uint32_t*)&ahi[o0 + c] = hw;  *(uint32_t*)&alo[o0 + c] = lw;
        split2(oacc[nv][2] * inv1, oacc[nv][3] * inv1, hw, lw);
        *(uint32_t*)&ahi[o1 + c] = hw;  *(uint32_t*)&alo[o1 + c] = lw;
    }
}

// ---------------------------------------------------------------------------
// Grid (global) attention via HMMA fp16x3, flash over 4 KV chunks (unchanged).
// ---------------------------------------------------------------------------
__global__ __launch_bounds__(256, 1) void grid_attn_mma(
    const float* __restrict__ qkv,
    __half* __restrict__ ahi, __half* __restrict__ alo)
{
    extern __shared__ __half gsm[];
    __half* sKh = gsm;
    __half* sKl = sKh + 256 * GA_KSTR;
    __half* sVh = sKl + 256 * GA_KSTR;
    __half* sVl = sVh + 32 * GA_VSTR;

    const int gidx = blockIdx.x;
    const int head = blockIdx.y + 4;
    const int bb   = blockIdx.z;
    const int iy = gidx >> 3, ix = gidx & 7;
    const int tid = threadIdx.x;
    const int w = tid >> 5, lane = tid & 31;
    const int rb = lane >> 2;
    const int kb = (lane & 3) * 2;

    for (int idx = tid; idx < 256 * 32; idx += 256) {
        int t = idx >> 5, d = idx & 31;
        int n = ((t >> 4) * 8 + iy) * kW + (t & 15) * 8 + ix;
        const float* row = qkv + ((size_t)bb * kN + n) * kQKV + head * kHD;
        __half h, l;
        split1(row[kC + d], h, l);     sKh[t * GA_KSTR + d] = h;  sKl[t * GA_KSTR + d] = l;
        split1(row[2 * kC + d], h, l); sVh[d * GA_VSTR + t] = h;  sVl[d * GA_VSTR + t] = l;
    }

    uint32_t qh[2][2][4], ql[2][2][4];
#pragma unroll
    for (int mt = 0; mt < 2; mt++) {
        int r  = w * 32 + mt * 16 + rb;
        int r8 = r + 8;
        int nA = ((r  >> 4) * 8 + iy) * kW + (r  & 15) * 8 + ix;
        int nB = ((r8 >> 4) * 8 + iy) * kW + (r8 & 15) * 8 + ix;
        const float* qA = qkv + ((size_t)bb * kN + nA) * kQKV + head * kHD;
        const float* qB = qkv + ((size_t)bb * kN + nB) * kQKV + head * kHD;
#pragma unroll
        for (int kt = 0; kt < 2; kt++) {
            float2 f;
            f = *(const float2*)&qA[kt * 16 + kb];
            split2(f.x * kScale, f.y * kScale, qh[mt][kt][0], ql[mt][kt][0]);
            f = *(const float2*)&qB[kt * 16 + kb];
            split2(f.x * kScale, f.y * kScale, qh[mt][kt][1], ql[mt][kt][1]);
            f = *(const float2*)&qA[kt * 16 + kb + 8];
            split2(f.x * kScale, f.y * kScale, qh[mt][kt][2], ql[mt][kt][2]);
            f = *(const float2*)&qB[kt * 16 + kb + 8];
            split2(f.x * kScale, f.y * kScale, qh[mt][kt][3], ql[mt][kt][3]);
        }
    }
    __syncthreads();

    float m_[4] = {-1e30f, -1e30f, -1e30f, -1e30f};
    float l_[4] = {0.f, 0.f, 0.f, 0.f};
    float oacc[2][4][4];
#pragma unroll
    for (int mt = 0; mt < 2; mt++)
#pragma unroll
        for (int nv = 0; nv < 4; nv++)
#pragma unroll
            for (int i = 0; i < 4; i++) oacc[mt][nv][i] = 0.f;

    for (int ch = 0; ch < 4; ch++) {
        float sacc[2][8][4];
#pragma unroll
        for (int mt = 0; mt < 2; mt++)
#pragma unroll
            for (int nt = 0; nt < 8; nt++)
#pragma unroll
                for (int i = 0; i < 4; i++) sacc[mt][nt][i] = 0.f;

#pragma unroll
        for (int nt = 0; nt < 8; nt++) {
#pragma unroll
            for (int kt = 0; kt < 2; kt++) {
                int kbase = (ch * 64 + nt * 8 + rb) * GA_KSTR + kt * 16 + kb;
                uint32_t kfh[2] = {*(const uint32_t*)&sKh[kbase],
                                   *(const uint32_t*)&sKh[kbase + 8]};
                uint32_t kfl[2] = {*(const uint32_t*)&sKl[kbase],
                                   *(const uint32_t*)&sKl[kbase + 8]};
#pragma unroll
                for (int mt = 0; mt < 2; mt++) {
                    mma16816(sacc[mt][nt], qh[mt][kt], kfh);
                    mma16816(sacc[mt][nt], qh[mt][kt], kfl);
                    mma16816(sacc[mt][nt], ql[mt][kt], kfh);
                }
            }
        }

#pragma unroll
        for (int mt = 0; mt < 2; mt++) {
            int i0 = 2 * mt, i1 = 2 * mt + 1;
            float cm0 = -1e30f, cm1 = -1e30f;
#pragma unroll
            for (int nt = 0; nt < 8; nt++) {
                cm0 = fmaxf(cm0, fmaxf(sacc[mt][nt][0], sacc[mt][nt][1]));
                cm1 = fmaxf(cm1, fmaxf(sacc[mt][nt][2], sacc[mt][nt][3]));
            }
            cm0 = fmaxf(cm0, __shfl_xor_sync(0xffffffffu, cm0, 1));
            cm0 = fmaxf(cm0, __shfl_xor_sync(0xffffffffu, cm0, 2));
            cm1 = fmaxf(cm1, __shfl_xor_sync(0xffffffffu, cm1, 1));
            cm1 = fmaxf(cm1, __shfl_xor_sync(0xffffffffu, cm1, 2));

            float nm0 = fmaxf(m_[i0], cm0);
            float nm1 = fmaxf(m_[i1], cm1);
            float corr0 = __expf(m_[i0] - nm0);
            float corr1 = __expf(m_[i1] - nm1);
            m_[i0] = nm0; m_[i1] = nm1;

            float s0 = 0.f, s1 = 0.f;
#pragma unroll
            for (int nt = 0; nt < 8; nt++) {
                sacc[mt][nt][0] = __expf(sacc[mt][nt][0] - nm0);
                sacc[mt][nt][1] = __expf(sacc[mt][nt][1] - nm0);
                sacc[mt][nt][2] = __expf(sacc[mt][nt][2] - nm1);
                sacc[mt][nt][3] = __expf(sacc[mt][nt][3] - nm1);
                s0 += sacc[mt][nt][0] + sacc[mt][nt][1];
                s1 += sacc[mt][nt][2] + sacc[mt][nt][3];
            }
            s0 += __shfl_xor_sync(0xffffffffu, s0, 1);
            s0 += __shfl_xor_sync(0xffffffffu, s0, 2);
            s1 += __shfl_xor_sync(0xffffffffu, s1, 1);
            s1 += __shfl_xor_sync(0xffffffffu, s1, 2);
            l_[i0] = l_[i0] * corr0 + s0;
            l_[i1] = l_[i1] * corr1 + s1;

#pragma unroll
            for (int nv = 0; nv < 4; nv++) {
                oacc[mt][nv][0] *= corr0;
                oacc[mt][nv][1] *= corr0;
                oacc[mt][nv][2] *= corr1;
                oacc[mt][nv][3] *= corr1;
            }

#pragma unroll
            for (int kt = 0; kt < 4; kt++) {
                uint32_t ph[4], pl[4];
                split2(sacc[mt][2 * kt][0],     sacc[mt][2 * kt][1],     ph[0], pl[0]);
                split2(sacc[mt][2 * kt][2],     sacc[mt][2 * kt][3],     ph[1], pl[1]);
                split2(sacc[mt][2 * kt + 1][0], sacc[mt][2 * kt + 1][1], ph[2], pl[2]);
                split2(sacc[mt][2 * kt + 1][2], sacc[mt][2 * kt + 1][3], ph[3], pl[3]);
#pragma unroll
                for (int nv = 0; nv < 4; nv++) {
                    int vbase = (nv * 8 + rb) * GA_VSTR + ch * 64 + kt * 16 + kb;
                    uint32_t vfh[2] = {*(const uint32_t*)&sVh[vbase],
                                       *(const uint32_t*)&sVh[vbase + 8]};
                    uint32_t vfl[2] = {*(const uint32_t*)&sVl[vbase],
                                       *(const uint32_t*)&sVl[vbase + 8]};
                    mma16816(oacc[mt][nv], ph, vfh);
                    mma16816(oacc[mt][nv], ph, vfl);
                    mma16816(oacc[mt][nv], pl, vfh);
                }
            }
        }
    }

#pragma unroll
    for (int mt = 0; mt < 2; mt++) {
        float inv0 = 1.f / l_[2 * mt];
        float inv1 = 1.f / l_[2 * mt + 1];
        int r  = w * 32 + mt * 16 + rb;
        int r8 = r + 8;
        int nA = ((r  >> 4) * 8 + iy) * kW + (r  & 15) * 8 + ix;
        int nB = ((r8 >> 4) * 8 + iy) * kW + (r8 & 15) * 8 + ix;
        size_t oA = ((size_t)bb * kN + nA) * kC + head * kHD + kb;
        size_t oB = ((size_t)bb * kN + nB) * kC + head * kHD + kb;
#pragma unroll
        for (int nv = 0; nv < 4; nv++) {
            int c = nv * 8;
            uint32_t hw, lw;
            split2(oacc[mt][nv][0] * inv0, oacc[mt][nv][1] * inv0, hw, lw);
            *(uint32_t*)&ahi[oA + c] = hw;  *(uint32_t*)&alo[oA + c] = lw;
            split2(oacc[mt][nv][2] * inv1, oacc[mt][nv][3] * inv1, hw, lw);
            *(uint32_t*)&ahi[oB + c] = hw;  *(uint32_t*)&alo[oB + c] = lw;
        }
    }
}

// ---------------------------------------------------------------------------
extern "C" void kernel_launch(void* const* d_in, const int* in_sizes, int n_in,
                              void* d_out, int out_size)
{
    const float* x     = (const float*)d_in[0];
    const float* Wqkv  = (const float*)d_in[1];
    const float* Wproj = (const float*)d_in[2];
    const float* bproj = (const float*)d_in[3];
    float* out = (float*)d_out;

    float* qkv;  cudaGetSymbolAddress((void**)&qkv, g_qkv);
    __half *xhi, *xlo, *a_hi, *a_lo, *wqhi, *wqlo, *wphi, *wplo;
    cudaGetSymbolAddress((void**)&xhi,  g_x_hi);
    cudaGetSymbolAddress((void**)&xlo,  g_x_lo);
    cudaGetSymbolAddress((void**)&a_hi, g_a_hi);
    cudaGetSymbolAddress((void**)&a_lo, g_a_lo);
    cudaGetSymbolAddress((void**)&wqhi, g_wq_hi);
    cudaGetSymbolAddress((void**)&wqlo, g_wq_lo);
    cudaGetSymbolAddress((void**)&wphi, g_wp_hi);
    cudaGetSymbolAddress((void**)&wplo, g_wp_lo);

    cudaFuncSetAttribute(gemm_mma, cudaFuncAttributeMaxDynamicSharedMemorySize, SMEM_GEMM);
    cudaFuncSetAttribute(grid_attn_mma,
                         cudaFuncAttributeMaxDynamicSharedMemorySize, GA_SMEM);

    // 0) conversions
    {
        int n = kM * kC;
        split_fp32_kernel<<<(n / 4 + 255) / 256, 256>>>(x, xhi, xlo, n);
        transpose_split_kernel<<<(kQKV * kC + 255) / 256, 256>>>(Wqkv, wqhi, wqlo, kC, kQKV);
        transpose_split_kernel<<<(kC * kC + 255) / 256, 256>>>(Wproj, wphi, wplo, kC, kC);
    }

    // 1) qkv = x @ W_qkv   (HMMA fp16x3, pipelined)
    gemm_mma<<<dim3(kQKV / BN, kM / BM), 256, SMEM_GEMM>>>(
        xhi, xlo, wqhi, wqlo, qkv, kQKV, nullptr);

    // 2a) local window attention (heads 0..3)
    local_attn_mma<<<dim3(256, 4, kB), 128>>>(qkv, a_hi, a_lo);

    // 2b) global grid attention (heads 4..7)
    grid_attn_mma<<<dim3(64, 4, kB), 256, GA_SMEM>>>(qkv, a_hi, a_lo);

    // 3) out = attn @ W_proj + b_proj   (HMMA fp16x3, pipelined)
    gemm_mma<<<dim3(kC / BN, kM / BM), 256, SMEM_GEMM>>>(
        a_hi, a_lo, wphi, wplo, out, kC, bproj);
}

// round 17
// speedup vs baseline: 2.6854x; 1.0422x over previous
#include <cuda_runtime.h>
#include <cuda_fp16.h>
#include <cstdint>

namespace {
constexpr int kB   = 8;
constexpr int kH   = 128;
constexpr int kW   = 128;
constexpr int kC   = 256;
constexpr int kN   = kH * kW;        // 16384 tokens per image
constexpr int kM   = kB * kN;        // 131072 rows
constexpr int kQKV = 3 * kC;         // 768
constexpr int kHD  = 32;             // head dim
constexpr float kScale = 0.17677669529663687f;  // 1/sqrt(32)

// GEMM tiling
constexpr int BM   = 128;
constexpr int BN   = 128;
constexpr int BK   = 32;             // K chunk (K total = 256, 8 chunks)
constexpr int LDSB = 40;             // halves per smem row (32 + 8 pad) = 80B
constexpr int ARRH = BM * LDSB;      // halves per array (5120)
constexpr int BUFH = 4 * ARRH;       // halves per buffer (4 arrays)
constexpr int SMEM_GEMM = 2 * BUFH * 2;  // 81920 bytes (double buffered)

// grid-attention smem (halves): K hi/lo [256][40], V^T hi/lo [32][264]
constexpr int GA_KSTR = 40;
constexpr int GA_VSTR = 264;
constexpr int GA_SMEM = (2 * 256 * GA_KSTR + 2 * 32 * GA_VSTR) * 2;  // 74752 B
}

// ---------------------------------------------------------------------------
// Scratch (device globals -- no allocations allowed)
// ---------------------------------------------------------------------------
__device__ float   g_qkv[(size_t)kM * kQKV];     // fp32 qkv for attention
__device__ __half  g_x_hi[(size_t)kM * kC];
__device__ __half  g_x_lo[(size_t)kM * kC];
__device__ __half  g_a_hi[(size_t)kM * kC];      // attention out hi
__device__ __half  g_a_lo[(size_t)kM * kC];      // attention out lo
__device__ __half  g_wq_hi[(size_t)kQKV * kC];   // W_qkv^T  [768][256]
__device__ __half  g_wq_lo[(size_t)kQKV * kC];
__device__ __half  g_wp_hi[(size_t)kC * kC];     // W_proj^T [256][256]
__device__ __half  g_wp_lo[(size_t)kC * kC];

// ---------------------------------------------------------------------------
__device__ __forceinline__ void split1(float v, __half& h, __half& l) {
    h = __float2half_rn(v);
    l = __float2half_rn(v - __half2float(h));
}
__device__ __forceinline__ uint32_t packh2(__half a, __half b) {
    __half2 t = __halves2half2(a, b);
    return *(uint32_t*)&t;
}
__device__ __forceinline__ void split2(float a, float b, uint32_t& hw, uint32_t& lw) {
    __half ha, la, hb, lb;
    split1(a, ha, la); split1(b, hb, lb);
    hw = packh2(ha, hb); lw = packh2(la, lb);
}

__device__ __forceinline__ void mma16816(float* c, const uint32_t* a, const uint32_t* b) {
    asm volatile(
        "mma.sync.aligned.m16n8k16.row.col.f32.f16.f16.f32 "
        "{%0,%1,%2,%3}, {%4,%5,%6,%7}, {%8,%9}, {%0,%1,%2,%3};"
        : "+f"(c[0]), "+f"(c[1]), "+f"(c[2]), "+f"(c[3])
        : "r"(a[0]), "r"(a[1]), "r"(a[2]), "r"(a[3]), "r"(b[0]), "r"(b[1]));
}

__device__ __forceinline__ uint32_t smem_u32(const void* p) {
    uint32_t a;
    asm("{ .reg .u64 t; cvta.to.shared.u64 t, %1; cvt.u32.u64 %0, t; }"
        : "=r"(a) : "l"(p));
    return a;
}
__device__ __forceinline__ void ldsm4(uint32_t* r, uint32_t addr) {
    asm volatile("ldmatrix.sync.aligned.m8n8.x4.shared.b16 {%0,%1,%2,%3}, [%4];"
        : "=r"(r[0]), "=r"(r[1]), "=r"(r[2]), "=r"(r[3]) : "r"(addr));
}
__device__ __forceinline__ void cp16(uint32_t s, const void* g) {
    asm volatile("cp.async.cg.shared.global [%0], [%1], 16;" :: "r"(s), "l"(g));
}
#define CP_COMMIT() asm volatile("cp.async.commit_group;" ::: "memory")
#define CP_WAIT(n)  asm volatile("cp.async.wait_group %0;" :: "n"(n) : "memory")

// ---------------------------------------------------------------------------
// Conversion kernels
// ---------------------------------------------------------------------------
__global__ void split_fp32_kernel(const float* __restrict__ src,
                                  __half* __restrict__ hi,
                                  __half* __restrict__ lo, int n)
{
    int i = (blockIdx.x * blockDim.x + threadIdx.x) * 4;
    if (i >= n) return;
    float4 v = *(const float4*)(src + i);
    uint32_t h0, l0, h1, l1;
    split2(v.x, v.y, h0, l0);
    split2(v.z, v.w, h1, l1);
    *(uint32_t*)(hi + i)     = h0;
    *(uint32_t*)(hi + i + 2) = h1;
    *(uint32_t*)(lo + i)     = l0;
    *(uint32_t*)(lo + i + 2) = l1;
}

__global__ void transpose_split_kernel(const float* __restrict__ W,
                                       __half* __restrict__ hi,
                                       __half* __restrict__ lo,
                                       int K, int N)
{
    int idx = blockIdx.x * blockDim.x + threadIdx.x;
    if (idx >= N * K) return;
    int nn = idx / K, kk = idx - nn * K;
    __half h, l;
    split1(W[(size_t)kk * N + nn], h, l);
    hi[idx] = h;
    lo[idx] = l;
}

// ---------------------------------------------------------------------------
// HMMA fp16x3 GEMM, double-buffered cp.async + ldmatrix, 2 CTAs/SM.
// C[M x Nd] = (Ahi+Alo)[M x 256] @ (Bhi+Blo)^T (+ bias)
// CTA tile 128x128, 8 warps in 4(M) x 2(N): warp tile 32x64.
// ---------------------------------------------------------------------------
__global__ __launch_bounds__(256, 2) void gemm_mma(
    const __half* __restrict__ Ahi, const __half* __restrict__ Alo,
    const __half* __restrict__ Bhi, const __half* __restrict__ Blo,
    float* __restrict__ C, int Nd, const float* __restrict__ bias)
{
    extern __shared__ __half sm[];

    const int tid  = threadIdx.x;
    const int wid  = tid >> 5;
    const int lane = tid & 31;
    const int wm   = wid & 3;
    const int wn   = wid >> 2;
    const int row0 = blockIdx.y * BM;
    const int col0 = blockIdx.x * BN;

    // staging coordinates: 512 uint4 per array, 256 threads x 2
    const int sr0 = tid >> 2;              // row for it=0 (0..63)
    const int sc  = (tid & 3) * 8;         // half offset (0,8,16,24)

    // ldmatrix lane mappings
    const int a_row  = lane & 15;                 // A: 16-row tile
    const int a_koff = (lane >> 4) << 3;          // 0 or 8
    const int b_nrow = ((lane >> 4) << 3) + (lane & 7);  // B: 16 n-rows
    const int b_koff = ((lane >> 3) & 1) << 3;    // 0 or 8

    const uint32_t smem0 = smem_u32(sm);

    float acc[2][8][4];
#pragma unroll
    for (int mt = 0; mt < 2; mt++)
#pragma unroll
        for (int nt = 0; nt < 8; nt++)
#pragma unroll
            for (int i = 0; i < 4; i++) acc[mt][nt][i] = 0.f;

    auto issue = [&](int ch, int buf) {
        uint32_t base = smem0 + (uint32_t)(buf * BUFH) * 2;
#pragma unroll
        for (int it = 0; it < 2; it++) {
            int r = sr0 + it * 64;
            uint32_t so = (uint32_t)(r * LDSB + sc) * 2;
            size_t ga = (size_t)(row0 + r) * kC + ch * BK + sc;
            size_t gb = (size_t)(col0 + r) * kC + ch * BK + sc;
            cp16(base + so,                Ahi + ga);
            cp16(base + ARRH * 2 + so,     Alo + ga);
            cp16(base + 2 * ARRH * 2 + so, Bhi + gb);
            cp16(base + 3 * ARRH * 2 + so, Blo + gb);
        }
        CP_COMMIT();
    };

    issue(0, 0);

    for (int ch = 0; ch < 8; ch++) {
        const int buf = ch & 1;
        if (ch + 1 < 8) {
            issue(ch + 1, buf ^ 1);
            CP_WAIT(1);
        } else {
            CP_WAIT(0);
        }
        __syncthreads();

        const uint32_t base = smem0 + (uint32_t)(buf * BUFH) * 2;

#pragma unroll
        for (int ks = 0; ks < BK / 16; ks++) {
            const int koff = ks * 16;

            uint32_t ah[2][4], al[2][4];
#pragma unroll
            for (int mt = 0; mt < 2; mt++) {
                uint32_t aoff =
                    (uint32_t)((wm * 32 + mt * 16 + a_row) * LDSB + koff + a_koff) * 2;
                ldsm4(ah[mt], base + aoff);
                ldsm4(al[mt], base + ARRH * 2 + aoff);
            }
#pragma unroll
            for (int ng = 0; ng < 4; ng++) {   // each ng covers n-tiles 2ng, 2ng+1
                uint32_t boff =
                    (uint32_t)((wn * 64 + ng * 16 + b_nrow) * LDSB + koff + b_koff) * 2;
                uint32_t bh[4], bl[4];
                ldsm4(bh, base + 2 * ARRH * 2 + boff);
                ldsm4(bl, base + 3 * ARRH * 2 + boff);
#pragma unroll
                for (int mt = 0; mt < 2; mt++) {
                    mma16816(acc[mt][2 * ng],     ah[mt], bh);
                    mma16816(acc[mt][2 * ng],     ah[mt], bl);
                    mma16816(acc[mt][2 * ng],     al[mt], bh);
                    mma16816(acc[mt][2 * ng + 1], ah[mt], bh + 2);
                    mma16816(acc[mt][2 * ng + 1], ah[mt], bl + 2);
                    mma16816(acc[mt][2 * ng + 1], al[mt], bh + 2);
                }
            }
        }
        __syncthreads();
    }

#pragma unroll
    for (int mt = 0; mt < 2; mt++) {
        int row = row0 + wm * 32 + mt * 16 + (lane >> 2);
#pragma unroll
        for (int nt = 0; nt < 8; nt++) {
            int col = col0 + wn * 64 + nt * 8 + (lane & 3) * 2;
            float2 v0 = make_float2(acc[mt][nt][0], acc[mt][nt][1]);
            float2 v1 = make_float2(acc[mt][nt][2], acc[mt][nt][3]);
            if (bias) {
                float b0 = bias[col], b1 = bias[col + 1];
                v0.x += b0; v0.y += b1;
                v1.x += b0; v1.y += b1;
            }
            *(float2*)&C[(size_t)row * Nd + col]       = v0;
            *(float2*)&C[(size_t)(row + 8) * Nd + col] = v1;
        }
    }
}

// ---------------------------------------------------------------------------
// Local (window) attention via HMMA fp16x3 (unchanged, passing).
// ---------------------------------------------------------------------------
__global__ __launch_bounds__(128) void local_attn_mma(
    const float* __restrict__ qkv,
    __half* __restrict__ ahi, __half* __restrict__ alo)
{
    __shared__ __half sQh[64 * 40], sQl[64 * 40];
    __shared__ __half sKh[64 * 40], sKl[64 * 40];
    __shared__ __half sVh[32 * 72], sVl[32 * 72];

    const int widx = blockIdx.x;
    const int head = blockIdx.y;
    const int bb   = blockIdx.z;
    const int wy = widx >> 4, wx = widx & 15;
    const int tid = threadIdx.x;
    const int w = tid >> 5, lane = tid & 31;
    const int rb = lane >> 2;
    const int kb = (lane & 3) * 2;

    for (int idx = tid; idx < 64 * 32; idx += 128) {
        int s = idx >> 5, d = idx & 31;
        int n = (wy * 8 + (s >> 3)) * kW + wx * 8 + (s & 7);
        const float* row = qkv + ((size_t)bb * kN + n) * kQKV + head * kHD;
        __half h, l;
        split1(row[d] * kScale, h, l);  sQh[s * 40 + d] = h;  sQl[s * 40 + d] = l;
        split1(row[kC + d], h, l);      sKh[s * 40 + d] = h;  sKl[s * 40 + d] = l;
        split1(row[2 * kC + d], h, l);  sVh[d * 72 + s] = h;  sVl[d * 72 + s] = l;
    }
    __syncthreads();

    uint32_t qh[2][4], ql[2][4];
#pragma unroll
    for (int kt = 0; kt < 2; kt++) {
        int base = (w * 16 + rb) * 40 + kt * 16 + kb;
        qh[kt][0] = *(const uint32_t*)&sQh[base];
        qh[kt][1] = *(const uint32_t*)&sQh[base + 8 * 40];
        qh[kt][2] = *(const uint32_t*)&sQh[base + 8];
        qh[kt][3] = *(const uint32_t*)&sQh[base + 8 * 40 + 8];
        ql[kt][0] = *(const uint32_t*)&sQl[base];
        ql[kt][1] = *(const uint32_t*)&sQl[base + 8 * 40];
        ql[kt][2] = *(const uint32_t*)&sQl[base + 8];
        ql[kt][3] = *(const uint32_t*)&sQl[base + 8 * 40 + 8];
    }

    float sacc[8][4];
#pragma unroll
    for (int nt = 0; nt < 8; nt++)
#pragma unroll
        for (int i = 0; i < 4; i++) sacc[nt][i] = 0.f;

#pragma unroll
    for (int nt = 0; nt < 8; nt++) {
#pragma unroll
        for (int kt = 0; kt < 2; kt++) {
            int kbase = (nt * 8 + rb) * 40 + kt * 16 + kb;
            uint32_t kfh[2] = {*(const uint32_t*)&sKh[kbase],
                               *(const uint32_t*)&sKh[kbase + 8]};
            uint32_t kfl[2] = {*(const uint32_t*)&sKl[kbase],
                               *(const uint32_t*)&sKl[kbase + 8]};
            mma16816(sacc[nt], qh[kt], kfh);
            mma16816(sacc[nt], qh[kt], kfl);
            mma16816(sacc[nt], ql[kt], kfh);
        }
    }

    float mx0 = -1e30f, mx1 = -1e30f;
#pragma unroll
    for (int nt = 0; nt < 8; nt++) {
        mx0 = fmaxf(mx0, fmaxf(sacc[nt][0], sacc[nt][1]));
        mx1 = fmaxf(mx1, fmaxf(sacc[nt][2], sacc[nt][3]));
    }
    mx0 = fmaxf(mx0, __shfl_xor_sync(0xffffffffu, mx0, 1));
    mx0 = fmaxf(mx0, __shfl_xor_sync(0xffffffffu, mx0, 2));
    mx1 = fmaxf(mx1, __shfl_xor_sync(0xffffffffu, mx1, 1));
    mx1 = fmaxf(mx1, __shfl_xor_sync(0xffffffffu, mx1, 2));

    float sum0 = 0.f, sum1 = 0.f;
#pragma unroll
    for (int nt = 0; nt < 8; nt++) {
        sacc[nt][0] = __expf(sacc[nt][0] - mx0);
        sacc[nt][1] = __expf(sacc[nt][1] - mx0);
        sacc[nt][2] = __expf(sacc[nt][2] - mx1);
        sacc[nt][3] = __expf(sacc[nt][3] - mx1);
        sum0 += sacc[nt][0] + sacc[nt][1];
        sum1 += sacc[nt][2] + sacc[nt][3];
    }
    sum0 += __shfl_xor_sync(0xffffffffu, sum0, 1);
    sum0 += __shfl_xor_sync(0xffffffffu, sum0, 2);
    sum1 += __shfl_xor_sync(0xffffffffu, sum1, 1);
    sum1 += __shfl_xor_sync(0xffffffffu, sum1, 2);

    float oacc[4][4];
#pragma unroll
    for (int nt = 0; nt < 4; nt++)
#pragma unroll
        for (int i = 0; i < 4; i++) oacc[nt][i] = 0.f;

#pragma unroll
    for (int kt = 0; kt < 4; kt++) {
        uint32_t ph[4], pl[4];
        split2(sacc[2 * kt][0],     sacc[2 * kt][1],     ph[0], pl[0]);
        split2(sacc[2 * kt][2],     sacc[2 * kt][3],     ph[1], pl[1]);
        split2(sacc[2 * kt + 1][0], sacc[2 * kt + 1][1], ph[2], pl[2]);
        split2(sacc[2 * kt + 1][2], sacc[2 * kt + 1][3], ph[3], pl[3]);
#pragma unroll
        for (int nv = 0; nv < 4; nv++) {
            int vbase = (nv * 8 + rb) * 72 + kt * 16 + kb;
            uint32_t vfh[2] = {*(const uint32_t*)&sVh[vbase],
                               *(const uint32_t*)&sVh[vbase + 8]};
            uint32_t vfl[2] = {*(const uint32_t*)&sVl[vbase],
                               *(const uint32_t*)&sVl[vbase + 8]};
            mma16816(oacc[nv], ph, vfh);
            mma16816(oacc[nv], ph, vfl);
            mma16816(oacc[nv], pl, vfh);
        }
    }

    const float inv0 = 1.f / sum0, inv1 = 1.f / sum1;
    int s0 = w * 16 + rb;
    int s1 = s0 + 8;
    int n0 = (wy * 8 + (s0 >> 3)) * kW + wx * 8 + (s0 & 7);
    int n1 = (wy * 8 + (s1 >> 3)) * kW + wx * 8 + (s1 & 7);
    size_t o0 = ((size_t)bb * kN + n0) * kC + head * kHD + kb;
    size_t o1 = ((size_t)bb * kN + n1) * kC + head * kHD + kb;
#pragma unroll
    for (int nv = 0; nv < 4; nv++) {
        int c = nv * 8;
        uint32_t hw, lw;
        split2(oacc[nv][0] * inv0, oacc[nv][1] * inv0, hw, lw);
        *(uint32_t*)&ahi[o0 + c] = hw;  *(uint32_t*)&alo[o0 + c] = lw;
        split2(oacc[nv][2] * inv1, oacc[nv][3] * inv1, hw, lw);
        *(uint32_t*)&ahi[o1 + c] = hw;  *(uint32_t*)&alo[o1 + c] = lw;
    }
}

// ---------------------------------------------------------------------------
// Grid (global) attention via HMMA fp16x3, flash over 4 KV chunks (unchanged).
// ---------------------------------------------------------------------------
__global__ __launch_bounds__(256, 1) void grid_attn_mma(
    const float* __restrict__ qkv,
    __half* __restrict__ ahi, __half* __restrict__ alo)
{
    extern __shared__ __half gsm[];
    __half* sKh = gsm;
    __half* sKl = sKh + 256 * GA_KSTR;
    __half* sVh = sKl + 256 * GA_KSTR;
    __half* sVl = sVh + 32 * GA_VSTR;

    const int gidx = blockIdx.x;
    const int head = blockIdx.y + 4;
    const int bb   = blockIdx.z;
    const int iy = gidx >> 3, ix = gidx & 7;
    const int tid = threadIdx.x;
    const int w = tid >> 5, lane = tid & 31;
    const int rb = lane >> 2;
    const int kb = (lane & 3) * 2;

    for (int idx = tid; idx < 256 * 32; idx += 256) {
        int t = idx >> 5, d = idx & 31;
        int n = ((t >> 4) * 8 + iy) * kW + (t & 15) * 8 + ix;
        const float* row = qkv + ((size_t)bb * kN + n) * kQKV + head * kHD;
        __half h, l;
        split1(row[kC + d], h, l);     sKh[t * GA_KSTR + d] = h;  sKl[t * GA_KSTR + d] = l;
        split1(row[2 * kC + d], h, l); sVh[d * GA_VSTR + t] = h;  sVl[d * GA_VSTR + t] = l;
    }

    uint32_t qh[2][2][4], ql[2][2][4];
#pragma unroll
    for (int mt = 0; mt < 2; mt++) {
        int r  = w * 32 + mt * 16 + rb;
        int r8 = r + 8;
        int nA = ((r  >> 4) * 8 + iy) * kW + (r  & 15) * 8 + ix;
        int nB = ((r8 >> 4) * 8 + iy) * kW + (r8 & 15) * 8 + ix;
        const float* qA = qkv + ((size_t)bb * kN + nA) * kQKV + head * kHD;
        const float* qB = qkv + ((size_t)bb * kN + nB) * kQKV + head * kHD;
#pragma unroll
        for (int kt = 0; kt < 2; kt++) {
            float2 f;
            f = *(const float2*)&qA[kt * 16 + kb];
            split2(f.x * kScale, f.y * kScale, qh[mt][kt][0], ql[mt][kt][0]);
            f = *(const float2*)&qB[kt * 16 + kb];
            split2(f.x * kScale, f.y * kScale, qh[mt][kt][1], ql[mt][kt][1]);
            f = *(const float2*)&qA[kt * 16 + kb + 8];
            split2(f.x * kScale, f.y * kScale, qh[mt][kt][2], ql[mt][kt][2]);
            f = *(const float2*)&qB[kt * 16 + kb + 8];
            split2(f.x * kScale, f.y * kScale, qh[mt][kt][3], ql[mt][kt][3]);
        }
    }
    __syncthreads();

    float m_[4] = {-1e30f, -1e30f, -1e30f, -1e30f};
    float l_[4] = {0.f, 0.f, 0.f, 0.f};
    float oacc[2][4][4];
#pragma unroll
    for (int mt = 0; mt < 2; mt++)
#pragma unroll
        for (int nv = 0; nv < 4; nv++)
#pragma unroll
            for (int i = 0; i < 4; i++) oacc[mt][nv][i] = 0.f;

    for (int ch = 0; ch < 4; ch++) {
        float sacc[2][8][4];
#pragma unroll
        for (int mt = 0; mt < 2; mt++)
#pragma unroll
            for (int nt = 0; nt < 8; nt++)
#pragma unroll
                for (int i = 0; i < 4; i++) sacc[mt][nt][i] = 0.f;

#pragma unroll
        for (int nt = 0; nt < 8; nt++) {
#pragma unroll
            for (int kt = 0; kt < 2; kt++) {
                int kbase = (ch * 64 + nt * 8 + rb) * GA_KSTR + kt * 16 + kb;
                uint32_t kfh[2] = {*(const uint32_t*)&sKh[kbase],
                                   *(const uint32_t*)&sKh[kbase + 8]};
                uint32_t kfl[2] = {*(const uint32_t*)&sKl[kbase],
                                   *(const uint32_t*)&sKl[kbase + 8]};
#pragma unroll
                for (int mt = 0; mt < 2; mt++) {
                    mma16816(sacc[mt][nt], qh[mt][kt], kfh);
                    mma16816(sacc[mt][nt], qh[mt][kt], kfl);
                    mma16816(sacc[mt][nt], ql[mt][kt], kfh);
                }
            }
        }

#pragma unroll
        for (int mt = 0; mt < 2; mt++) {
            int i0 = 2 * mt, i1 = 2 * mt + 1;
            float cm0 = -1e30f, cm1 = -1e30f;
#pragma unroll
            for (int nt = 0; nt < 8; nt++) {
                cm0 = fmaxf(cm0, fmaxf(sacc[mt][nt][0], sacc[mt][nt][1]));
                cm1 = fmaxf(cm1, fmaxf(sacc[mt][nt][2], sacc[mt][nt][3]));
            }
            cm0 = fmaxf(cm0, __shfl_xor_sync(0xffffffffu, cm0, 1));
            cm0 = fmaxf(cm0, __shfl_xor_sync(0xffffffffu, cm0, 2));
            cm1 = fmaxf(cm1, __shfl_xor_sync(0xffffffffu, cm1, 1));
            cm1 = fmaxf(cm1, __shfl_xor_sync(0xffffffffu, cm1, 2));

            float nm0 = fmaxf(m_[i0], cm0);
            float nm1 = fmaxf(m_[i1], cm1);
            float corr0 = __expf(m_[i0] - nm0);
            float corr1 = __expf(m_[i1] - nm1);
            m_[i0] = nm0; m_[i1] = nm1;

            float s0 = 0.f, s1 = 0.f;
#pragma unroll
            for (int nt = 0; nt < 8; nt++) {
                sacc[mt][nt][0] = __expf(sacc[mt][nt][0] - nm0);
                sacc[mt][nt][1] = __expf(sacc[mt][nt][1] - nm0);
                sacc[mt][nt][2] = __expf(sacc[mt][nt][2] - nm1);
                sacc[mt][nt][3] = __expf(sacc[mt][nt][3] - nm1);
                s0 += sacc[mt][nt][0] + sacc[mt][nt][1];
                s1 += sacc[mt][nt][2] + sacc[mt][nt][3];
            }
            s0 += __shfl_xor_sync(0xffffffffu, s0, 1);
            s0 += __shfl_xor_sync(0xffffffffu, s0, 2);
            s1 += __shfl_xor_sync(0xffffffffu, s1, 1);
            s1 += __shfl_xor_sync(0xffffffffu, s1, 2);
            l_[i0] = l_[i0] * corr0 + s0;
            l_[i1] = l_[i1] * corr1 + s1;

#pragma unroll
            for (int nv = 0; nv < 4; nv++) {
                oacc[mt][nv][0] *= corr0;
                oacc[mt][nv][1] *= corr0;
                oacc[mt][nv][2] *= corr1;
                oacc[mt][nv][3] *= corr1;
            }

#pragma unroll
            for (int kt = 0; kt < 4; kt++) {
                uint32_t ph[4], pl[4];
                split2(sacc[mt][2 * kt][0],     sacc[mt][2 * kt][1],     ph[0], pl[0]);
                split2(sacc[mt][2 * kt][2],     sacc[mt][2 * kt][3],     ph[1], pl[1]);
                split2(sacc[mt][2 * kt + 1][0], sacc[mt][2 * kt + 1][1], ph[2], pl[2]);
                split2(sacc[mt][2 * kt + 1][2], sacc[mt][2 * kt + 1][3], ph[3], pl[3]);
#pragma unroll
                for (int nv = 0; nv < 4; nv++) {
                    int vbase = (nv * 8 + rb) * GA_VSTR + ch * 64 + kt * 16 + kb;
                    uint32_t vfh[2] = {*(const uint32_t*)&sVh[vbase],
                                       *(const uint32_t*)&sVh[vbase + 8]};
                    uint32_t vfl[2] = {*(const uint32_t*)&sVl[vbase],
                                       *(const uint32_t*)&sVl[vbase + 8]};
                    mma16816(oacc[mt][nv], ph, vfh);
                    mma16816(oacc[mt][nv], ph, vfl);
                    mma16816(oacc[mt][nv], pl, vfh);
                }
            }
        }
    }

#pragma unroll
    for (int mt = 0; mt < 2; mt++) {
        float inv0 = 1.f / l_[2 * mt];
        float inv1 = 1.f / l_[2 * mt + 1];
        int r  = w * 32 + mt * 16 + rb;
        int r8 = r + 8;
        int nA = ((r  >> 4) * 8 + iy) * kW + (r  & 15) * 8 + ix;
        int nB = ((r8 >> 4) * 8 + iy) * kW + (r8 & 15) * 8 + ix;
        size_t oA = ((size_t)bb * kN + nA) * kC + head * kHD + kb;
        size_t oB = ((size_t)bb * kN + nB) * kC + head * kHD + kb;
#pragma unroll
        for (int nv = 0; nv < 4; nv++) {
            int c = nv * 8;
            uint32_t hw, lw;
            split2(oacc[mt][nv][0] * inv0, oacc[mt][nv][1] * inv0, hw, lw);
            *(uint32_t*)&ahi[oA + c] = hw;  *(uint32_t*)&alo[oA + c] = lw;
            split2(oacc[mt][nv][2] * inv1, oacc[mt][nv][3] * inv1, hw, lw);
            *(uint32_t*)&ahi[oB + c] = hw;  *(uint32_t*)&alo[oB + c] = lw;
        }
    }
}

// ---------------------------------------------------------------------------
extern "C" void kernel_launch(void* const* d_in, const int* in_sizes, int n_in,
                              void* d_out, int out_size)
{
    const float* x     = (const float*)d_in[0];
    const float* Wqkv  = (const float*)d_in[1];
    const float* Wproj = (const float*)d_in[2];
    const float* bproj = (const float*)d_in[3];
    float* out = (float*)d_out;

    float* qkv;  cudaGetSymbolAddress((void**)&qkv, g_qkv);
    __half *xhi, *xlo, *a_hi, *a_lo, *wqhi, *wqlo, *wphi, *wplo;
    cudaGetSymbolAddress((void**)&xhi,  g_x_hi);
    cudaGetSymbolAddress((void**)&xlo,  g_x_lo);
    cudaGetSymbolAddress((void**)&a_hi, g_a_hi);
    cudaGetSymbolAddress((void**)&a_lo, g_a_lo);
    cudaGetSymbolAddress((void**)&wqhi, g_wq_hi);
    cudaGetSymbolAddress((void**)&wqlo, g_wq_lo);
    cudaGetSymbolAddress((void**)&wphi, g_wp_hi);
    cudaGetSymbolAddress((void**)&wplo, g_wp_lo);

    cudaFuncSetAttribute(gemm_mma, cudaFuncAttributeMaxDynamicSharedMemorySize, SMEM_GEMM);
    cudaFuncSetAttribute(grid_attn_mma,
                         cudaFuncAttributeMaxDynamicSharedMemorySize, GA_SMEM);

    // 0) conversions
    {
        int n = kM * kC;
        split_fp32_kernel<<<(n / 4 + 255) / 256, 256>>>(x, xhi, xlo, n);
        transpose_split_kernel<<<(kQKV * kC + 255) / 256, 256>>>(Wqkv, wqhi, wqlo, kC, kQKV);
        transpose_split_kernel<<<(kC * kC + 255) / 256, 256>>>(Wproj, wphi, wplo, kC, kC);
    }

    // 1) qkv = x @ W_qkv   (HMMA fp16x3, pipelined + ldmatrix)
    gemm_mma<<<dim3(kQKV / BN, kM / BM), 256, SMEM_GEMM>>>(
        xhi, xlo, wqhi, wqlo, qkv, kQKV, nullptr);

    // 2a) local window attention (heads 0..3)
    local_attn_mma<<<dim3(256, 4, kB), 128>>>(qkv, a_hi, a_lo);

    // 2b) global grid attention (heads 4..7)
    grid_attn_mma<<<dim3(64, 4, kB), 256, GA_SMEM>>>(qkv, a_hi, a_lo);

    // 3) out = attn @ W_proj + b_proj   (HMMA fp16x3, pipelined + ldmatrix)
    gemm_mma<<<dim3(kC / BN, kM / BM), 256, SMEM_GEMM>>>(
        a_hi, a_lo, wphi, wplo, out, kC, bproj);
}